// round 11
// baseline (speedup 1.0000x reference)
#include <cuda_runtime.h>
#include <cuda_fp16.h>
#include <math.h>
#include <stdint.h>

// Problem constants
#define BB 2
#define TT 2048
#define EE 1024
#define HH 16
#define HD 64
#define DFF 4096
#define NTOK (BB*TT)          // 4096
#define BHN (BB*HH)           // 32

// ---------------- scratch (device globals) ----------------
__device__ float  g_h   [NTOK*EE];     // LN1 fp32 (residual)
__device__ __half g_hh  [NTOK*EE];     // LN1 fp16 (GEMM A)
__device__ __half g_wqkv[EE*3*EE];     // packed fp16 [E,3E]
__device__ __half g_qkv [NTOK*3*EE];   // fp16
__device__ __half g_o   [NTOK*EE];     // fp16
__device__ float  g_x2  [NTOK*EE];     // fp32
__device__ float  g_h2  [NTOK*EE];     // LN2 fp32 (residual)
__device__ __half g_h2h [NTOK*EE];     // LN2 fp16
__device__ __half g_ffn [NTOK*DFF];    // fp16
__device__ __half g_wp  [EE*EE];
__device__ __half g_w1  [EE*DFF];
__device__ __half g_w2  [DFF*EE];

// ---------------- helpers ----------------
__device__ __forceinline__ void cp16(void* s, const void* g) {
    uint32_t sa = (uint32_t)__cvta_generic_to_shared(s);
    asm volatile("cp.async.cg.shared.global [%0], [%1], 16;" :: "r"(sa), "l"(g));
}
__device__ __forceinline__ void cp_commit() { asm volatile("cp.async.commit_group;"); }
template<int N> __device__ __forceinline__ void cp_wait() {
    asm volatile("cp.async.wait_group %0;" :: "n"(N));
}
__device__ __forceinline__ void ldsm_x4(uint32_t r[4], const void* p) {
    uint32_t a = (uint32_t)__cvta_generic_to_shared(p);
    asm volatile("ldmatrix.sync.aligned.m8n8.x4.shared.b16 {%0,%1,%2,%3}, [%4];"
        : "=r"(r[0]), "=r"(r[1]), "=r"(r[2]), "=r"(r[3]) : "r"(a));
}
__device__ __forceinline__ void ldsm_x4t(uint32_t r[4], const void* p) {
    uint32_t a = (uint32_t)__cvta_generic_to_shared(p);
    asm volatile("ldmatrix.sync.aligned.m8n8.x4.trans.shared.b16 {%0,%1,%2,%3}, [%4];"
        : "=r"(r[0]), "=r"(r[1]), "=r"(r[2]), "=r"(r[3]) : "r"(a));
}
__device__ __forceinline__ void mma_f16(float acc[4], const uint32_t a[4], const uint32_t b[2]) {
    asm volatile(
        "mma.sync.aligned.m16n8k16.row.col.f32.f16.f16.f32 "
        "{%0,%1,%2,%3},{%4,%5,%6,%7},{%8,%9},{%0,%1,%2,%3};"
        : "+f"(acc[0]), "+f"(acc[1]), "+f"(acc[2]), "+f"(acc[3])
        : "r"(a[0]), "r"(a[1]), "r"(a[2]), "r"(a[3]), "r"(b[0]), "r"(b[1]));
}
__device__ __forceinline__ float ex2(float x) {
    float r;
    asm("ex2.approx.ftz.f32 %0, %1;" : "=f"(r) : "f"(x));
    return r;
}

// ---------------- LayerNorm: fp32 + fp16 outputs ----------------
__global__ void ln_kernel(const float* __restrict__ x,
                          const float* __restrict__ gamma,
                          const float* __restrict__ beta,
                          float* __restrict__ yf,
                          __half* __restrict__ yh)
{
    int row = blockIdx.x;
    const float* xr = x + (size_t)row * EE;
    float* yfr = yf + (size_t)row * EE;
    __half* yhr = yh + (size_t)row * EE;
    int tid = threadIdx.x;
    __shared__ float red[256];

    float s = 0.f;
    for (int i = tid; i < EE; i += 256) s += xr[i];
    red[tid] = s; __syncthreads();
    for (int o = 128; o > 0; o >>= 1) { if (tid < o) red[tid] += red[tid + o]; __syncthreads(); }
    float mean = red[0] * (1.0f / EE);
    __syncthreads();

    float v = 0.f;
    for (int i = tid; i < EE; i += 256) { float d = xr[i] - mean; v += d * d; }
    red[tid] = v; __syncthreads();
    for (int o = 128; o > 0; o >>= 1) { if (tid < o) red[tid] += red[tid + o]; __syncthreads(); }
    float inv = rsqrtf(red[0] * (1.0f / EE) + 1e-5f);

    for (int i = tid; i < EE; i += 256) {
        float val = (xr[i] - mean) * inv * gamma[i] + beta[i];
        yfr[i] = val;
        yhr[i] = __float2half(val);
    }
}

// ---------------- convert weights fp32 -> fp16 ----------------
__global__ void cvtw_kernel(const float4* __restrict__ in, __half2* __restrict__ out, int n4)
{
    int i = blockIdx.x * blockDim.x + threadIdx.x;
    if (i >= n4) return;
    float4 v = in[i];
    out[2 * i]     = __floats2half2_rn(v.x, v.y);
    out[2 * i + 1] = __floats2half2_rn(v.z, v.w);
}

// ---------------- pack wq/wk/wv [H,E,hd] -> fp16 [E, 3E] ----------------
__global__ void pack_w_kernel(const float* __restrict__ wq,
                              const float* __restrict__ wk,
                              const float* __restrict__ wv,
                              __half* __restrict__ out)
{
    int idx = blockIdx.x * blockDim.x + threadIdx.x;
    const int total = 3 * EE * EE;
    if (idx >= total) return;
    int part = idx / (EE * EE);
    int rem  = idx % (EE * EE);
    int e = rem / EE;
    int c = rem % EE;
    const float* w = (part == 0) ? wq : (part == 1) ? wk : wv;
    out[(size_t)e * (3 * EE) + part * EE + c] =
        __float2half(w[(size_t)(c >> 6) * (EE * HD) + (size_t)e * HD + (c & 63)]);
}

// ---------------- fp16 GEMM v2: CTA 256x128x32, warp tile 64x64 -------------
// 8 warps (4x2). 1 CTA/SM. EPI: 0 none; 2 relu+bias; 3 +bias+res.
#define MM_SMEM2 (2*256*40*2 + 2*32*136*2)   // 58368 B

template <int EPI, bool HOUT>
__global__ void __launch_bounds__(256, 1)
mm_fp16(const __half* __restrict__ A,
        const __half* __restrict__ B,
        const float* __restrict__ bias,
        const float* __restrict__ res,
        void* __restrict__ Cout,
        int M, int N, int K)
{
    extern __shared__ __half smh[];
    __half (*As)[256][40]  = reinterpret_cast<__half(*)[256][40]>(smh);
    __half (*Bs)[32][136]  = reinterpret_cast<__half(*)[32][136]>(smh + 2 * 256 * 40);

    int tid = threadIdx.x;
    int lane = tid & 31, wid = tid >> 5;
    int wm = wid >> 1, wn = wid & 1;      // 4 x 2
    int g = lane >> 2, c = lane & 3;
    int rowBase = blockIdx.y * 256;
    int colBase = blockIdx.x * 128;

    float acc[4][8][4];
    #pragma unroll
    for (int i = 0; i < 4; i++)
        #pragma unroll
        for (int j = 0; j < 8; j++)
            #pragma unroll
            for (int k = 0; k < 4; k++) acc[i][j][k] = 0.f;

    auto load_stage = [&](int buf, int kk) {
        // A: 256x32 fp16 = 1024 chunks
        #pragma unroll
        for (int i = 0; i < 4; i++) {
            int idx = i * 256 + tid;
            int m = idx >> 2, ch = idx & 3;
            cp16(&As[buf][m][ch * 8], A + (size_t)(rowBase + m) * K + kk + ch * 8);
        }
        // B: 32x128 fp16 = 512 chunks
        #pragma unroll
        for (int i = 0; i < 2; i++) {
            int idx = i * 256 + tid;
            int r = idx >> 4, ch = idx & 15;
            cp16(&Bs[buf][r][ch * 8], B + (size_t)(kk + r) * N + colBase + ch * 8);
        }
        cp_commit();
    };

    load_stage(0, 0);
    int nk = K / 32;
    for (int k0 = 0; k0 < nk; k0++) {
        int cur = k0 & 1;
        if (k0 + 1 < nk) { load_stage(cur ^ 1, (k0 + 1) * 32); cp_wait<1>(); }
        else            { cp_wait<0>(); }
        __syncthreads();

        #pragma unroll
        for (int ks = 0; ks < 2; ks++) {
            int kb = ks * 16;
            uint32_t af[4][4];
            #pragma unroll
            for (int mt = 0; mt < 4; mt++) {
                int m0 = wm * 64 + mt * 16;
                ldsm_x4(af[mt], &As[cur][m0 + (lane & 15)][kb + ((lane >> 4) << 3)]);
            }
            uint32_t bf[8][2];
            #pragma unroll
            for (int np = 0; np < 4; np++) {
                int n0 = wn * 64 + np * 16;
                uint32_t q[4];
                ldsm_x4t(q, &Bs[cur][kb + (lane & 15)][n0 + ((lane >> 4) << 3)]);
                bf[2*np][0]   = q[0]; bf[2*np][1]   = q[1];
                bf[2*np+1][0] = q[2]; bf[2*np+1][1] = q[3];
            }
            #pragma unroll
            for (int mt = 0; mt < 4; mt++)
                #pragma unroll
                for (int nt = 0; nt < 8; nt++)
                    mma_f16(acc[mt][nt], af[mt], bf[nt]);
        }
        __syncthreads();
    }

    #pragma unroll
    for (int mt = 0; mt < 4; mt++) {
        int row0 = rowBase + wm * 64 + mt * 16 + g;
        #pragma unroll
        for (int nt = 0; nt < 8; nt++) {
            int col = colBase + wn * 64 + nt * 8 + c * 2;
            float v0 = acc[mt][nt][0], v1 = acc[mt][nt][1];
            float v2 = acc[mt][nt][2], v3 = acc[mt][nt][3];
            if (EPI >= 1) {
                float b0 = bias[col], b1 = bias[col + 1];
                v0 += b0; v1 += b1; v2 += b0; v3 += b1;
            }
            if (EPI == 2) {
                v0 = fmaxf(v0, 0.f); v1 = fmaxf(v1, 0.f);
                v2 = fmaxf(v2, 0.f); v3 = fmaxf(v3, 0.f);
            }
            if (EPI == 3) {
                v0 += res[(size_t)row0 * N + col];
                v1 += res[(size_t)row0 * N + col + 1];
                v2 += res[(size_t)(row0 + 8) * N + col];
                v3 += res[(size_t)(row0 + 8) * N + col + 1];
            }
            if (HOUT) {
                __half* Ch = (__half*)Cout;
                *reinterpret_cast<__half2*>(&Ch[(size_t)row0 * N + col])       = __floats2half2_rn(v0, v1);
                *reinterpret_cast<__half2*>(&Ch[(size_t)(row0 + 8) * N + col]) = __floats2half2_rn(v2, v3);
            } else {
                float* Cf = (float*)Cout;
                *reinterpret_cast<float2*>(&Cf[(size_t)row0 * N + col])       = make_float2(v0, v1);
                *reinterpret_cast<float2*>(&Cf[(size_t)(row0 + 8) * N + col]) = make_float2(v2, v3);
            }
        }
    }
}

// ---------------- fused flash attention (R8, unchanged) ----------
__global__ void __launch_bounds__(128)
flash_kernel(const __half* __restrict__ qkv, __half* __restrict__ o)
{
    __shared__ __half KP[2][64][72];
    __shared__ __half Vs[2][64][72];

    int bh = blockIdx.y;
    int b = bh >> 4, h = bh & 15;
    int rt = gridDim.x - 1 - blockIdx.x;
    int q0 = rt * 64;

    int tid = threadIdx.x;
    int lane = tid & 31, wid = tid >> 5;
    int g = lane >> 2, c = lane & 3;
    int wbase = wid * 16;
    const int S3E = 3 * EE;

    auto load_tile = [&](int buf, int st) {
        const __half* Kg = qkv + (size_t)(b * TT + st * 64) * S3E + EE + h * HD;
        const __half* Vg = Kg + EE;
        #pragma unroll
        for (int i = 0; i < 4; i++) {
            int idx = i * 128 + tid;
            int r = idx >> 3, ch = idx & 7;
            cp16(&KP[buf][r][ch * 8], Kg + (size_t)r * S3E + ch * 8);
            cp16(&Vs[buf][r][ch * 8], Vg + (size_t)r * S3E + ch * 8);
        }
        cp_commit();
    };

    load_tile(0, 0);

    uint32_t qf[4][4];
    {
        const __half* Qb = qkv + (size_t)(b * TT + q0 + wbase) * S3E + h * HD;
        const float qs = 0.125f * 1.4426950408889634f;
        const __half2 sc = __floats2half2_rn(qs, qs);
        #pragma unroll
        for (int ks = 0; ks < 4; ks++) {
            int kb = ks * 16;
            __half2 t0 = __hmul2(*(const __half2*)(Qb + (size_t)g       * S3E + kb + 2 * c),     sc);
            __half2 t1 = __hmul2(*(const __half2*)(Qb + (size_t)(g + 8) * S3E + kb + 2 * c),     sc);
            __half2 t2 = __hmul2(*(const __half2*)(Qb + (size_t)g       * S3E + kb + 2 * c + 8), sc);
            __half2 t3 = __hmul2(*(const __half2*)(Qb + (size_t)(g + 8) * S3E + kb + 2 * c + 8), sc);
            qf[ks][0] = *reinterpret_cast<uint32_t*>(&t0);
            qf[ks][1] = *reinterpret_cast<uint32_t*>(&t1);
            qf[ks][2] = *reinterpret_cast<uint32_t*>(&t2);
            qf[ks][3] = *reinterpret_cast<uint32_t*>(&t3);
        }
    }

    float m0 = -INFINITY, m1 = -INFINITY, l0 = 0.f, l1 = 0.f;
    float oacc[8][4];
    #pragma unroll
    for (int nt = 0; nt < 8; nt++)
        #pragma unroll
        for (int k = 0; k < 4; k++) oacc[nt][k] = 0.f;

    for (int st = 0; st <= rt; st++) {
        int cur = st & 1;

        __syncthreads();
        if (st + 1 <= rt) { load_tile(cur ^ 1, st + 1); cp_wait<1>(); }
        else              { cp_wait<0>(); }
        __syncthreads();

        float sacc[8][4];
        #pragma unroll
        for (int nt = 0; nt < 8; nt++)
            #pragma unroll
            for (int k = 0; k < 4; k++) sacc[nt][k] = 0.f;

        #pragma unroll
        for (int ks = 0; ks < 4; ks++) {
            int kb = ks * 16;
            #pragma unroll
            for (int np = 0; np < 4; np++) {
                uint32_t q[4];
                ldsm_x4(q, &KP[cur][np * 16 + (lane & 7) + ((lane & 16) >> 1)][kb + (lane & 8)]);
                uint32_t b0[2] = {q[0], q[1]}, b1[2] = {q[2], q[3]};
                mma_f16(sacc[2 * np],     qf[ks], b0);
                mma_f16(sacc[2 * np + 1], qf[ks], b1);
            }
        }

        if (st == rt) {
            int ql0 = wbase + g, ql1 = ql0 + 8;
            #pragma unroll
            for (int nt = 0; nt < 8; nt++) {
                int kl = nt * 8 + 2 * c;
                if (kl     > ql0) sacc[nt][0] = -1e30f;
                if (kl + 1 > ql0) sacc[nt][1] = -1e30f;
                if (kl     > ql1) sacc[nt][2] = -1e30f;
                if (kl + 1 > ql1) sacc[nt][3] = -1e30f;
            }
        }

        float mx0 = -1e30f, mx1 = -1e30f;
        #pragma unroll
        for (int nt = 0; nt < 8; nt++) {
            mx0 = fmaxf(mx0, fmaxf(sacc[nt][0], sacc[nt][1]));
            mx1 = fmaxf(mx1, fmaxf(sacc[nt][2], sacc[nt][3]));
        }
        mx0 = fmaxf(mx0, __shfl_xor_sync(0xffffffffu, mx0, 1));
        mx0 = fmaxf(mx0, __shfl_xor_sync(0xffffffffu, mx0, 2));
        mx1 = fmaxf(mx1, __shfl_xor_sync(0xffffffffu, mx1, 1));
        mx1 = fmaxf(mx1, __shfl_xor_sync(0xffffffffu, mx1, 2));

        float mn0 = fmaxf(m0, mx0), mn1 = fmaxf(m1, mx1);
        float al0 = ex2(m0 - mn0), al1 = ex2(m1 - mn1);
        m0 = mn0; m1 = mn1;

        float rs0 = 0.f, rs1 = 0.f;
        #pragma unroll
        for (int nt = 0; nt < 8; nt++) {
            float p0 = ex2(sacc[nt][0] - m0);
            float p1 = ex2(sacc[nt][1] - m0);
            float p2 = ex2(sacc[nt][2] - m1);
            float p3 = ex2(sacc[nt][3] - m1);
            sacc[nt][0] = p0; sacc[nt][1] = p1; sacc[nt][2] = p2; sacc[nt][3] = p3;
            rs0 += p0 + p1; rs1 += p2 + p3;
        }
        rs0 += __shfl_xor_sync(0xffffffffu, rs0, 1);
        rs0 += __shfl_xor_sync(0xffffffffu, rs0, 2);
        rs1 += __shfl_xor_sync(0xffffffffu, rs1, 1);
        rs1 += __shfl_xor_sync(0xffffffffu, rs1, 2);
        l0 = l0 * al0 + rs0;
        l1 = l1 * al1 + rs1;

        #pragma unroll
        for (int nt = 0; nt < 8; nt++) {
            oacc[nt][0] *= al0; oacc[nt][1] *= al0;
            oacc[nt][2] *= al1; oacc[nt][3] *= al1;
        }

        __syncthreads();
        #pragma unroll
        for (int nt = 0; nt < 8; nt++) {
            int col = nt * 8 + 2 * c;
            *reinterpret_cast<__half2*>(&KP[cur][wbase + g    ][col]) = __floats2half2_rn(sacc[nt][0], sacc[nt][1]);
            *reinterpret_cast<__half2*>(&KP[cur][wbase + g + 8][col]) = __floats2half2_rn(sacc[nt][2], sacc[nt][3]);
        }
        __syncwarp();

        #pragma unroll
        for (int ks = 0; ks < 4; ks++) {
            int kb = ks * 16;
            uint32_t af[4];
            ldsm_x4(af, &KP[cur][wbase + (lane & 15)][kb + ((lane >> 4) << 3)]);
            #pragma unroll
            for (int np = 0; np < 4; np++) {
                uint32_t q[4];
                ldsm_x4t(q, &Vs[cur][kb + (lane & 15)][np * 16 + ((lane >> 4) << 3)]);
                uint32_t b0[2] = {q[0], q[1]}, b1[2] = {q[2], q[3]};
                mma_f16(oacc[2 * np],     af, b0);
                mma_f16(oacc[2 * np + 1], af, b1);
            }
        }
    }

    float i0 = 1.0f / l0, i1 = 1.0f / l1;
    __half* Ob = o + (size_t)(b * TT + q0 + wbase) * EE + h * HD;
    #pragma unroll
    for (int nt = 0; nt < 8; nt++) {
        int col = nt * 8 + 2 * c;
        *reinterpret_cast<__half2*>(&Ob[(size_t)g * EE + col]) =
            __floats2half2_rn(oacc[nt][0] * i0, oacc[nt][1] * i0);
        *reinterpret_cast<__half2*>(&Ob[(size_t)(g + 8) * EE + col]) =
            __floats2half2_rn(oacc[nt][2] * i1, oacc[nt][3] * i1);
    }
}

// ---------------- launcher ----------------
extern "C" void kernel_launch(void* const* d_in, const int* in_sizes, int n_in,
                              void* d_out, int out_size)
{
    const float* x      = (const float*)d_in[0];
    const float* wq     = (const float*)d_in[1];
    const float* wk     = (const float*)d_in[2];
    const float* wv     = (const float*)d_in[3];
    const float* w_proj = (const float*)d_in[4];
    const float* b_proj = (const float*)d_in[5];
    const float* gamma1 = (const float*)d_in[6];
    const float* beta1  = (const float*)d_in[7];
    const float* gamma2 = (const float*)d_in[8];
    const float* beta2  = (const float*)d_in[9];
    const float* w1     = (const float*)d_in[10];
    const float* b1     = (const float*)d_in[11];
    const float* w2     = (const float*)d_in[12];
    const float* b2     = (const float*)d_in[13];
    float* out = (float*)d_out;

    float *p_h, *p_x2, *p_h2;
    __half *p_hh, *p_wqkv, *p_qkv, *p_o, *p_h2h, *p_ffn, *p_wp, *p_w1, *p_w2;
    cudaGetSymbolAddress((void**)&p_h,    g_h);
    cudaGetSymbolAddress((void**)&p_hh,   g_hh);
    cudaGetSymbolAddress((void**)&p_wqkv, g_wqkv);
    cudaGetSymbolAddress((void**)&p_qkv,  g_qkv);
    cudaGetSymbolAddress((void**)&p_o,    g_o);
    cudaGetSymbolAddress((void**)&p_x2,   g_x2);
    cudaGetSymbolAddress((void**)&p_h2,   g_h2);
    cudaGetSymbolAddress((void**)&p_h2h,  g_h2h);
    cudaGetSymbolAddress((void**)&p_ffn,  g_ffn);
    cudaGetSymbolAddress((void**)&p_wp,   g_wp);
    cudaGetSymbolAddress((void**)&p_w1,   g_w1);
    cudaGetSymbolAddress((void**)&p_w2,   g_w2);

    cudaFuncSetAttribute(mm_fp16<0, true>,  cudaFuncAttributeMaxDynamicSharedMemorySize, MM_SMEM2);
    cudaFuncSetAttribute(mm_fp16<2, true>,  cudaFuncAttributeMaxDynamicSharedMemorySize, MM_SMEM2);
    cudaFuncSetAttribute(mm_fp16<3, false>, cudaFuncAttributeMaxDynamicSharedMemorySize, MM_SMEM2);

    // 1) LN1 (fp32 + fp16)
    ln_kernel<<<NTOK, 256>>>(x, gamma1, beta1, p_h, p_hh);
    // 2) pack + convert weights to fp16
    pack_w_kernel<<<(3 * EE * EE) / 256, 256>>>(wq, wk, wv, p_wqkv);
    cvtw_kernel<<<(EE * EE / 4 + 255) / 256, 256>>>((const float4*)w_proj, (__half2*)p_wp, EE * EE / 4);
    cvtw_kernel<<<(EE * DFF / 4 + 255) / 256, 256>>>((const float4*)w1, (__half2*)p_w1, EE * DFF / 4);
    cvtw_kernel<<<(DFF * EE / 4 + 255) / 256, 256>>>((const float4*)w2, (__half2*)p_w2, DFF * EE / 4);
    // 3) QKV = h @ Wqkv (fp16 out)
    mm_fp16<0, true><<<dim3(3 * EE / 128, NTOK / 256), 256, MM_SMEM2>>>(p_hh, p_wqkv, nullptr, nullptr, p_qkv, NTOK, 3 * EE, EE);
    // 4-6) fused flash attention (fp16)
    flash_kernel<<<dim3(TT / 64, BHN), 128>>>(p_qkv, p_o);
    // 7) x2 = h + O @ w_proj + b_proj (fp32 out)
    mm_fp16<3, false><<<dim3(EE / 128, NTOK / 256), 256, MM_SMEM2>>>(p_o, p_wp, b_proj, p_h, p_x2, NTOK, EE, EE);
    // 8) LN2 (fp32 + fp16)
    ln_kernel<<<NTOK, 256>>>(p_x2, gamma2, beta2, p_h2, p_h2h);
    // 9) ffn = relu(h2 @ w1 + b1) (fp16 out)
    mm_fp16<2, true><<<dim3(DFF / 128, NTOK / 256), 256, MM_SMEM2>>>(p_h2h, p_w1, b1, nullptr, p_ffn, NTOK, DFF, EE);
    // 10) out = h2 + ffn @ w2 + b2 (fp32 out)
    mm_fp16<3, false><<<dim3(EE / 128, NTOK / 256), 256, MM_SMEM2>>>(p_ffn, p_w2, b2, p_h2, out, NTOK, EE, DFF);
}

// round 12
// speedup vs baseline: 1.1358x; 1.1358x over previous
#include <cuda_runtime.h>
#include <cuda_fp16.h>
#include <math.h>
#include <stdint.h>

// Problem constants
#define BB 2
#define TT 2048
#define EE 1024
#define HH 16
#define HD 64
#define DFF 4096
#define NTOK (BB*TT)          // 4096
#define BHN (BB*HH)           // 32

// ---------------- scratch (device globals) ----------------
__device__ float  g_h   [NTOK*EE];     // LN1 fp32 (residual)
__device__ __half g_hh  [NTOK*EE];     // LN1 fp16 (GEMM A)
__device__ __half g_wqkv[EE*3*EE];     // packed fp16 [E,3E]
__device__ __half g_qkv [NTOK*3*EE];   // fp16
__device__ __half g_o   [NTOK*EE];     // fp16
__device__ float  g_x2  [NTOK*EE];     // fp32
__device__ float  g_h2  [NTOK*EE];     // LN2 fp32 (residual)
__device__ __half g_h2h [NTOK*EE];     // LN2 fp16
__device__ __half g_ffn [NTOK*DFF];    // fp16
__device__ __half g_wp  [EE*EE];
__device__ __half g_w1  [EE*DFF];
__device__ __half g_w2  [DFF*EE];

// ---------------- helpers ----------------
__device__ __forceinline__ void cp16(void* s, const void* g) {
    uint32_t sa = (uint32_t)__cvta_generic_to_shared(s);
    asm volatile("cp.async.cg.shared.global [%0], [%1], 16;" :: "r"(sa), "l"(g));
}
__device__ __forceinline__ void cp_commit() { asm volatile("cp.async.commit_group;"); }
template<int N> __device__ __forceinline__ void cp_wait() {
    asm volatile("cp.async.wait_group %0;" :: "n"(N));
}
__device__ __forceinline__ void ldsm_x4(uint32_t r[4], const void* p) {
    uint32_t a = (uint32_t)__cvta_generic_to_shared(p);
    asm volatile("ldmatrix.sync.aligned.m8n8.x4.shared.b16 {%0,%1,%2,%3}, [%4];"
        : "=r"(r[0]), "=r"(r[1]), "=r"(r[2]), "=r"(r[3]) : "r"(a));
}
__device__ __forceinline__ void ldsm_x4t(uint32_t r[4], const void* p) {
    uint32_t a = (uint32_t)__cvta_generic_to_shared(p);
    asm volatile("ldmatrix.sync.aligned.m8n8.x4.trans.shared.b16 {%0,%1,%2,%3}, [%4];"
        : "=r"(r[0]), "=r"(r[1]), "=r"(r[2]), "=r"(r[3]) : "r"(a));
}
__device__ __forceinline__ void mma_f16(float acc[4], const uint32_t a[4], const uint32_t b[2]) {
    asm volatile(
        "mma.sync.aligned.m16n8k16.row.col.f32.f16.f16.f32 "
        "{%0,%1,%2,%3},{%4,%5,%6,%7},{%8,%9},{%0,%1,%2,%3};"
        : "+f"(acc[0]), "+f"(acc[1]), "+f"(acc[2]), "+f"(acc[3])
        : "r"(a[0]), "r"(a[1]), "r"(a[2]), "r"(a[3]), "r"(b[0]), "r"(b[1]));
}
__device__ __forceinline__ float ex2(float x) {
    float r;
    asm("ex2.approx.ftz.f32 %0, %1;" : "=f"(r) : "f"(x));
    return r;
}

// ---------------- LayerNorm: fp32 + fp16 outputs ----------------
__global__ void ln_kernel(const float* __restrict__ x,
                          const float* __restrict__ gamma,
                          const float* __restrict__ beta,
                          float* __restrict__ yf,
                          __half* __restrict__ yh)
{
    int row = blockIdx.x;
    const float* xr = x + (size_t)row * EE;
    float* yfr = yf + (size_t)row * EE;
    __half* yhr = yh + (size_t)row * EE;
    int tid = threadIdx.x;
    __shared__ float red[256];

    float s = 0.f;
    for (int i = tid; i < EE; i += 256) s += xr[i];
    red[tid] = s; __syncthreads();
    for (int o = 128; o > 0; o >>= 1) { if (tid < o) red[tid] += red[tid + o]; __syncthreads(); }
    float mean = red[0] * (1.0f / EE);
    __syncthreads();

    float v = 0.f;
    for (int i = tid; i < EE; i += 256) { float d = xr[i] - mean; v += d * d; }
    red[tid] = v; __syncthreads();
    for (int o = 128; o > 0; o >>= 1) { if (tid < o) red[tid] += red[tid + o]; __syncthreads(); }
    float inv = rsqrtf(red[0] * (1.0f / EE) + 1e-5f);

    for (int i = tid; i < EE; i += 256) {
        float val = (xr[i] - mean) * inv * gamma[i] + beta[i];
        yfr[i] = val;
        yhr[i] = __float2half(val);
    }
}

// ---------------- convert weights fp32 -> fp16 ----------------
__global__ void cvtw_kernel(const float4* __restrict__ in, __half2* __restrict__ out, int n4)
{
    int i = blockIdx.x * blockDim.x + threadIdx.x;
    if (i >= n4) return;
    float4 v = in[i];
    out[2 * i]     = __floats2half2_rn(v.x, v.y);
    out[2 * i + 1] = __floats2half2_rn(v.z, v.w);
}

// ---------------- pack wq/wk/wv [H,E,hd] -> fp16 [E, 3E] ----------------
__global__ void pack_w_kernel(const float* __restrict__ wq,
                              const float* __restrict__ wk,
                              const float* __restrict__ wv,
                              __half* __restrict__ out)
{
    int idx = blockIdx.x * blockDim.x + threadIdx.x;
    const int total = 3 * EE * EE;
    if (idx >= total) return;
    int part = idx / (EE * EE);
    int rem  = idx % (EE * EE);
    int e = rem / EE;
    int c = rem % EE;
    const float* w = (part == 0) ? wq : (part == 1) ? wk : wv;
    out[(size_t)e * (3 * EE) + part * EE + c] =
        __float2half(w[(size_t)(c >> 6) * (EE * HD) + (size_t)e * HD + (c & 63)]);
}

// ---------------- fp16 GEMM: 128x128x32, 3-stage ring, 1 sync/iter ----------
// 8 warps (4x2), warp tile 32x64 via m16n8k16 (R8 compute body).
#define MM_SMEM3 ((3*128*40 + 3*32*136) * 2)   // 56832 B dynamic

template <int EPI, bool HOUT>
__global__ void __launch_bounds__(256, 2)
mm_fp16(const __half* __restrict__ A,
        const __half* __restrict__ B,
        const float* __restrict__ bias,
        const float* __restrict__ res,
        void* __restrict__ Cout,
        int M, int N, int K)
{
    extern __shared__ __half smh[];
    __half (*As)[128][40] = reinterpret_cast<__half(*)[128][40]>(smh);
    __half (*Bs)[32][136] = reinterpret_cast<__half(*)[32][136]>(smh + 3 * 128 * 40);

    int tid = threadIdx.x;
    int lane = tid & 31, wid = tid >> 5;
    int wm = wid >> 1, wn = wid & 1;
    int g = lane >> 2, c = lane & 3;
    int rowBase = blockIdx.y * 128;
    int colBase = blockIdx.x * 128;

    float acc[2][8][4];
    #pragma unroll
    for (int i = 0; i < 2; i++)
        #pragma unroll
        for (int j = 0; j < 8; j++)
            #pragma unroll
            for (int k = 0; k < 4; k++) acc[i][j][k] = 0.f;

    auto load_stage = [&](int buf, int kk) {
        #pragma unroll
        for (int i = 0; i < 2; i++) {
            int idx = i * 256 + tid;
            int m = idx >> 2, ch = idx & 3;
            cp16(&As[buf][m][ch * 8], A + (size_t)(rowBase + m) * K + kk + ch * 8);
        }
        #pragma unroll
        for (int i = 0; i < 2; i++) {
            int idx = i * 256 + tid;
            int r = idx >> 4, ch = idx & 15;
            cp16(&Bs[buf][r][ch * 8], B + (size_t)(kk + r) * N + colBase + ch * 8);
        }
        cp_commit();
    };

    int nk = K / 32;
    load_stage(0, 0);
    load_stage(1, 32);

    int cur = 0;
    for (int k0 = 0; k0 < nk; k0++) {
        cp_wait<1>();            // stage k0 resident (exactly 2 groups outstanding)
        __syncthreads();         // all warps done reading buffer (k0+2)%3 (iter k0-1)
        if (k0 + 2 < nk) load_stage((k0 + 2) % 3, (k0 + 2) * 32);
        else             cp_commit();   // empty group keeps wait arithmetic exact

        #pragma unroll
        for (int ks = 0; ks < 2; ks++) {
            int kb = ks * 16;
            uint32_t af[2][4];
            #pragma unroll
            for (int mt = 0; mt < 2; mt++) {
                int m0 = wm * 32 + mt * 16;
                ldsm_x4(af[mt], &As[cur][m0 + (lane & 15)][kb + ((lane >> 4) << 3)]);
            }
            uint32_t bf[8][2];
            #pragma unroll
            for (int np = 0; np < 4; np++) {
                int n0 = wn * 64 + np * 16;
                uint32_t q[4];
                ldsm_x4t(q, &Bs[cur][kb + (lane & 15)][n0 + ((lane >> 4) << 3)]);
                bf[2*np][0]   = q[0]; bf[2*np][1]   = q[1];
                bf[2*np+1][0] = q[2]; bf[2*np+1][1] = q[3];
            }
            #pragma unroll
            for (int mt = 0; mt < 2; mt++)
                #pragma unroll
                for (int nt = 0; nt < 8; nt++)
                    mma_f16(acc[mt][nt], af[mt], bf[nt]);
        }
        cur = (cur == 2) ? 0 : cur + 1;
    }

    #pragma unroll
    for (int mt = 0; mt < 2; mt++) {
        int row0 = rowBase + wm * 32 + mt * 16 + g;
        #pragma unroll
        for (int nt = 0; nt < 8; nt++) {
            int col = colBase + wn * 64 + nt * 8 + c * 2;
            float v0 = acc[mt][nt][0], v1 = acc[mt][nt][1];
            float v2 = acc[mt][nt][2], v3 = acc[mt][nt][3];
            if (EPI >= 1) {
                float b0 = bias[col], b1 = bias[col + 1];
                v0 += b0; v1 += b1; v2 += b0; v3 += b1;
            }
            if (EPI == 2) {
                v0 = fmaxf(v0, 0.f); v1 = fmaxf(v1, 0.f);
                v2 = fmaxf(v2, 0.f); v3 = fmaxf(v3, 0.f);
            }
            if (EPI == 3) {
                v0 += res[(size_t)row0 * N + col];
                v1 += res[(size_t)row0 * N + col + 1];
                v2 += res[(size_t)(row0 + 8) * N + col];
                v3 += res[(size_t)(row0 + 8) * N + col + 1];
            }
            if (HOUT) {
                __half* Ch = (__half*)Cout;
                *reinterpret_cast<__half2*>(&Ch[(size_t)row0 * N + col])       = __floats2half2_rn(v0, v1);
                *reinterpret_cast<__half2*>(&Ch[(size_t)(row0 + 8) * N + col]) = __floats2half2_rn(v2, v3);
            } else {
                float* Cf = (float*)Cout;
                *reinterpret_cast<float2*>(&Cf[(size_t)row0 * N + col])       = make_float2(v0, v1);
                *reinterpret_cast<float2*>(&Cf[(size_t)(row0 + 8) * N + col]) = make_float2(v2, v3);
            }
        }
    }
}

// ---------------- fused flash attention (R8, unchanged) ----------
__global__ void __launch_bounds__(128)
flash_kernel(const __half* __restrict__ qkv, __half* __restrict__ o)
{
    __shared__ __half KP[2][64][72];
    __shared__ __half Vs[2][64][72];

    int bh = blockIdx.y;
    int b = bh >> 4, h = bh & 15;
    int rt = gridDim.x - 1 - blockIdx.x;
    int q0 = rt * 64;

    int tid = threadIdx.x;
    int lane = tid & 31, wid = tid >> 5;
    int g = lane >> 2, c = lane & 3;
    int wbase = wid * 16;
    const int S3E = 3 * EE;

    auto load_tile = [&](int buf, int st) {
        const __half* Kg = qkv + (size_t)(b * TT + st * 64) * S3E + EE + h * HD;
        const __half* Vg = Kg + EE;
        #pragma unroll
        for (int i = 0; i < 4; i++) {
            int idx = i * 128 + tid;
            int r = idx >> 3, ch = idx & 7;
            cp16(&KP[buf][r][ch * 8], Kg + (size_t)r * S3E + ch * 8);
            cp16(&Vs[buf][r][ch * 8], Vg + (size_t)r * S3E + ch * 8);
        }
        cp_commit();
    };

    load_tile(0, 0);

    uint32_t qf[4][4];
    {
        const __half* Qb = qkv + (size_t)(b * TT + q0 + wbase) * S3E + h * HD;
        const float qs = 0.125f * 1.4426950408889634f;
        const __half2 sc = __floats2half2_rn(qs, qs);
        #pragma unroll
        for (int ks = 0; ks < 4; ks++) {
            int kb = ks * 16;
            __half2 t0 = __hmul2(*(const __half2*)(Qb + (size_t)g       * S3E + kb + 2 * c),     sc);
            __half2 t1 = __hmul2(*(const __half2*)(Qb + (size_t)(g + 8) * S3E + kb + 2 * c),     sc);
            __half2 t2 = __hmul2(*(const __half2*)(Qb + (size_t)g       * S3E + kb + 2 * c + 8), sc);
            __half2 t3 = __hmul2(*(const __half2*)(Qb + (size_t)(g + 8) * S3E + kb + 2 * c + 8), sc);
            qf[ks][0] = *reinterpret_cast<uint32_t*>(&t0);
            qf[ks][1] = *reinterpret_cast<uint32_t*>(&t1);
            qf[ks][2] = *reinterpret_cast<uint32_t*>(&t2);
            qf[ks][3] = *reinterpret_cast<uint32_t*>(&t3);
        }
    }

    float m0 = -INFINITY, m1 = -INFINITY, l0 = 0.f, l1 = 0.f;
    float oacc[8][4];
    #pragma unroll
    for (int nt = 0; nt < 8; nt++)
        #pragma unroll
        for (int k = 0; k < 4; k++) oacc[nt][k] = 0.f;

    for (int st = 0; st <= rt; st++) {
        int cur = st & 1;

        __syncthreads();
        if (st + 1 <= rt) { load_tile(cur ^ 1, st + 1); cp_wait<1>(); }
        else              { cp_wait<0>(); }
        __syncthreads();

        float sacc[8][4];
        #pragma unroll
        for (int nt = 0; nt < 8; nt++)
            #pragma unroll
            for (int k = 0; k < 4; k++) sacc[nt][k] = 0.f;

        #pragma unroll
        for (int ks = 0; ks < 4; ks++) {
            int kb = ks * 16;
            #pragma unroll
            for (int np = 0; np < 4; np++) {
                uint32_t q[4];
                ldsm_x4(q, &KP[cur][np * 16 + (lane & 7) + ((lane & 16) >> 1)][kb + (lane & 8)]);
                uint32_t b0[2] = {q[0], q[1]}, b1[2] = {q[2], q[3]};
                mma_f16(sacc[2 * np],     qf[ks], b0);
                mma_f16(sacc[2 * np + 1], qf[ks], b1);
            }
        }

        if (st == rt) {
            int ql0 = wbase + g, ql1 = ql0 + 8;
            #pragma unroll
            for (int nt = 0; nt < 8; nt++) {
                int kl = nt * 8 + 2 * c;
                if (kl     > ql0) sacc[nt][0] = -1e30f;
                if (kl + 1 > ql0) sacc[nt][1] = -1e30f;
                if (kl     > ql1) sacc[nt][2] = -1e30f;
                if (kl + 1 > ql1) sacc[nt][3] = -1e30f;
            }
        }

        float mx0 = -1e30f, mx1 = -1e30f;
        #pragma unroll
        for (int nt = 0; nt < 8; nt++) {
            mx0 = fmaxf(mx0, fmaxf(sacc[nt][0], sacc[nt][1]));
            mx1 = fmaxf(mx1, fmaxf(sacc[nt][2], sacc[nt][3]));
        }
        mx0 = fmaxf(mx0, __shfl_xor_sync(0xffffffffu, mx0, 1));
        mx0 = fmaxf(mx0, __shfl_xor_sync(0xffffffffu, mx0, 2));
        mx1 = fmaxf(mx1, __shfl_xor_sync(0xffffffffu, mx1, 1));
        mx1 = fmaxf(mx1, __shfl_xor_sync(0xffffffffu, mx1, 2));

        float mn0 = fmaxf(m0, mx0), mn1 = fmaxf(m1, mx1);
        float al0 = ex2(m0 - mn0), al1 = ex2(m1 - mn1);
        m0 = mn0; m1 = mn1;

        float rs0 = 0.f, rs1 = 0.f;
        #pragma unroll
        for (int nt = 0; nt < 8; nt++) {
            float p0 = ex2(sacc[nt][0] - m0);
            float p1 = ex2(sacc[nt][1] - m0);
            float p2 = ex2(sacc[nt][2] - m1);
            float p3 = ex2(sacc[nt][3] - m1);
            sacc[nt][0] = p0; sacc[nt][1] = p1; sacc[nt][2] = p2; sacc[nt][3] = p3;
            rs0 += p0 + p1; rs1 += p2 + p3;
        }
        rs0 += __shfl_xor_sync(0xffffffffu, rs0, 1);
        rs0 += __shfl_xor_sync(0xffffffffu, rs0, 2);
        rs1 += __shfl_xor_sync(0xffffffffu, rs1, 1);
        rs1 += __shfl_xor_sync(0xffffffffu, rs1, 2);
        l0 = l0 * al0 + rs0;
        l1 = l1 * al1 + rs1;

        #pragma unroll
        for (int nt = 0; nt < 8; nt++) {
            oacc[nt][0] *= al0; oacc[nt][1] *= al0;
            oacc[nt][2] *= al1; oacc[nt][3] *= al1;
        }

        __syncthreads();
        #pragma unroll
        for (int nt = 0; nt < 8; nt++) {
            int col = nt * 8 + 2 * c;
            *reinterpret_cast<__half2*>(&KP[cur][wbase + g    ][col]) = __floats2half2_rn(sacc[nt][0], sacc[nt][1]);
            *reinterpret_cast<__half2*>(&KP[cur][wbase + g + 8][col]) = __floats2half2_rn(sacc[nt][2], sacc[nt][3]);
        }
        __syncwarp();

        #pragma unroll
        for (int ks = 0; ks < 4; ks++) {
            int kb = ks * 16;
            uint32_t af[4];
            ldsm_x4(af, &KP[cur][wbase + (lane & 15)][kb + ((lane >> 4) << 3)]);
            #pragma unroll
            for (int np = 0; np < 4; np++) {
                uint32_t q[4];
                ldsm_x4t(q, &Vs[cur][kb + (lane & 15)][np * 16 + ((lane >> 4) << 3)]);
                uint32_t b0[2] = {q[0], q[1]}, b1[2] = {q[2], q[3]};
                mma_f16(oacc[2 * np],     af, b0);
                mma_f16(oacc[2 * np + 1], af, b1);
            }
        }
    }

    float i0 = 1.0f / l0, i1 = 1.0f / l1;
    __half* Ob = o + (size_t)(b * TT + q0 + wbase) * EE + h * HD;
    #pragma unroll
    for (int nt = 0; nt < 8; nt++) {
        int col = nt * 8 + 2 * c;
        *reinterpret_cast<__half2*>(&Ob[(size_t)g * EE + col]) =
            __floats2half2_rn(oacc[nt][0] * i0, oacc[nt][1] * i0);
        *reinterpret_cast<__half2*>(&Ob[(size_t)(g + 8) * EE + col]) =
            __floats2half2_rn(oacc[nt][2] * i1, oacc[nt][3] * i1);
    }
}

// ---------------- launcher ----------------
extern "C" void kernel_launch(void* const* d_in, const int* in_sizes, int n_in,
                              void* d_out, int out_size)
{
    const float* x      = (const float*)d_in[0];
    const float* wq     = (const float*)d_in[1];
    const float* wk     = (const float*)d_in[2];
    const float* wv     = (const float*)d_in[3];
    const float* w_proj = (const float*)d_in[4];
    const float* b_proj = (const float*)d_in[5];
    const float* gamma1 = (const float*)d_in[6];
    const float* beta1  = (const float*)d_in[7];
    const float* gamma2 = (const float*)d_in[8];
    const float* beta2  = (const float*)d_in[9];
    const float* w1     = (const float*)d_in[10];
    const float* b1     = (const float*)d_in[11];
    const float* w2     = (const float*)d_in[12];
    const float* b2     = (const float*)d_in[13];
    float* out = (float*)d_out;

    float *p_h, *p_x2, *p_h2;
    __half *p_hh, *p_wqkv, *p_qkv, *p_o, *p_h2h, *p_ffn, *p_wp, *p_w1, *p_w2;
    cudaGetSymbolAddress((void**)&p_h,    g_h);
    cudaGetSymbolAddress((void**)&p_hh,   g_hh);
    cudaGetSymbolAddress((void**)&p_wqkv, g_wqkv);
    cudaGetSymbolAddress((void**)&p_qkv,  g_qkv);
    cudaGetSymbolAddress((void**)&p_o,    g_o);
    cudaGetSymbolAddress((void**)&p_x2,   g_x2);
    cudaGetSymbolAddress((void**)&p_h2,   g_h2);
    cudaGetSymbolAddress((void**)&p_h2h,  g_h2h);
    cudaGetSymbolAddress((void**)&p_ffn,  g_ffn);
    cudaGetSymbolAddress((void**)&p_wp,   g_wp);
    cudaGetSymbolAddress((void**)&p_w1,   g_w1);
    cudaGetSymbolAddress((void**)&p_w2,   g_w2);

    cudaFuncSetAttribute(mm_fp16<0, true>,  cudaFuncAttributeMaxDynamicSharedMemorySize, MM_SMEM3);
    cudaFuncSetAttribute(mm_fp16<2, true>,  cudaFuncAttributeMaxDynamicSharedMemorySize, MM_SMEM3);
    cudaFuncSetAttribute(mm_fp16<3, false>, cudaFuncAttributeMaxDynamicSharedMemorySize, MM_SMEM3);

    // 1) LN1 (fp32 + fp16)
    ln_kernel<<<NTOK, 256>>>(x, gamma1, beta1, p_h, p_hh);
    // 2) pack + convert weights to fp16
    pack_w_kernel<<<(3 * EE * EE) / 256, 256>>>(wq, wk, wv, p_wqkv);
    cvtw_kernel<<<(EE * EE / 4 + 255) / 256, 256>>>((const float4*)w_proj, (__half2*)p_wp, EE * EE / 4);
    cvtw_kernel<<<(EE * DFF / 4 + 255) / 256, 256>>>((const float4*)w1, (__half2*)p_w1, EE * DFF / 4);
    cvtw_kernel<<<(DFF * EE / 4 + 255) / 256, 256>>>((const float4*)w2, (__half2*)p_w2, DFF * EE / 4);
    // 3) QKV = h @ Wqkv (fp16 out)
    mm_fp16<0, true><<<dim3(3 * EE / 128, NTOK / 128), 256, MM_SMEM3>>>(p_hh, p_wqkv, nullptr, nullptr, p_qkv, NTOK, 3 * EE, EE);
    // 4-6) fused flash attention (fp16)
    flash_kernel<<<dim3(TT / 64, BHN), 128>>>(p_qkv, p_o);
    // 7) x2 = h + O @ w_proj + b_proj (fp32 out)
    mm_fp16<3, false><<<dim3(EE / 128, NTOK / 128), 256, MM_SMEM3>>>(p_o, p_wp, b_proj, p_h, p_x2, NTOK, EE, EE);
    // 8) LN2 (fp32 + fp16)
    ln_kernel<<<NTOK, 256>>>(p_x2, gamma2, beta2, p_h2, p_h2h);
    // 9) ffn = relu(h2 @ w1 + b1) (fp16 out)
    mm_fp16<2, true><<<dim3(DFF / 128, NTOK / 128), 256, MM_SMEM3>>>(p_h2h, p_w1, b1, nullptr, p_ffn, NTOK, DFF, EE);
    // 10) out = h2 + ffn @ w2 + b2 (fp32 out)
    mm_fp16<3, false><<<dim3(EE / 128, NTOK / 128), 256, MM_SMEM3>>>(p_ffn, p_w2, b2, p_h2, out, NTOK, EE, DFF);
}

// round 13
// speedup vs baseline: 1.1863x; 1.0444x over previous
#include <cuda_runtime.h>
#include <cuda_fp16.h>
#include <math.h>
#include <stdint.h>

// Problem constants
#define BB 2
#define TT 2048
#define EE 1024
#define HH 16
#define HD 64
#define DFF 4096
#define NTOK (BB*TT)          // 4096
#define BHN (BB*HH)           // 32

// ---------------- scratch (device globals) ----------------
__device__ __half g_hh  [NTOK*EE];     // LN1 fp16 (GEMM A + residual)
__device__ __half g_wqkv[EE*3*EE];     // packed fp16 [E,3E]
__device__ __half g_qkv [NTOK*3*EE];   // fp16
__device__ __half g_o   [NTOK*EE];     // fp16
__device__ float  g_x2  [NTOK*EE];     // fp32 (LN2 input)
__device__ __half g_h2h [NTOK*EE];     // LN2 fp16 (GEMM A + residual)
__device__ __half g_ffn [NTOK*DFF];    // fp16
__device__ __half g_wp  [EE*EE];
__device__ __half g_w1  [EE*DFF];
__device__ __half g_w2  [DFF*EE];

// ---------------- helpers ----------------
__device__ __forceinline__ void cp16(void* s, const void* g) {
    uint32_t sa = (uint32_t)__cvta_generic_to_shared(s);
    asm volatile("cp.async.cg.shared.global [%0], [%1], 16;" :: "r"(sa), "l"(g));
}
__device__ __forceinline__ void cp_commit() { asm volatile("cp.async.commit_group;"); }
template<int N> __device__ __forceinline__ void cp_wait() {
    asm volatile("cp.async.wait_group %0;" :: "n"(N));
}
__device__ __forceinline__ void ldsm_x4(uint32_t r[4], const void* p) {
    uint32_t a = (uint32_t)__cvta_generic_to_shared(p);
    asm volatile("ldmatrix.sync.aligned.m8n8.x4.shared.b16 {%0,%1,%2,%3}, [%4];"
        : "=r"(r[0]), "=r"(r[1]), "=r"(r[2]), "=r"(r[3]) : "r"(a));
}
__device__ __forceinline__ void ldsm_x4t(uint32_t r[4], const void* p) {
    uint32_t a = (uint32_t)__cvta_generic_to_shared(p);
    asm volatile("ldmatrix.sync.aligned.m8n8.x4.trans.shared.b16 {%0,%1,%2,%3}, [%4];"
        : "=r"(r[0]), "=r"(r[1]), "=r"(r[2]), "=r"(r[3]) : "r"(a));
}
__device__ __forceinline__ void mma_f16(float acc[4], const uint32_t a[4], const uint32_t b[2]) {
    asm volatile(
        "mma.sync.aligned.m16n8k16.row.col.f32.f16.f16.f32 "
        "{%0,%1,%2,%3},{%4,%5,%6,%7},{%8,%9},{%0,%1,%2,%3};"
        : "+f"(acc[0]), "+f"(acc[1]), "+f"(acc[2]), "+f"(acc[3])
        : "r"(a[0]), "r"(a[1]), "r"(a[2]), "r"(a[3]), "r"(b[0]), "r"(b[1]));
}
__device__ __forceinline__ float ex2(float x) {
    float r;
    asm("ex2.approx.ftz.f32 %0, %1;" : "=f"(r) : "f"(x));
    return r;
}

// ---------------- LayerNorm: single pass, fp16 output only ----------------
// 256 threads, each owns exactly 4 elements (one float4) of the 1024-row.
__global__ void ln_kernel(const float* __restrict__ x,
                          const float* __restrict__ gamma,
                          const float* __restrict__ beta,
                          __half* __restrict__ yh)
{
    int row = blockIdx.x;
    int tid = threadIdx.x;
    const float4* xr = reinterpret_cast<const float4*>(x + (size_t)row * EE);
    __half2* yr = reinterpret_cast<__half2*>(yh + (size_t)row * EE);
    __shared__ float rs[256], rq[256];

    float4 v = xr[tid];
    float s  = v.x + v.y + v.z + v.w;
    float q  = v.x * v.x + v.y * v.y + v.z * v.z + v.w * v.w;
    rs[tid] = s; rq[tid] = q;
    __syncthreads();
    for (int o = 128; o > 0; o >>= 1) {
        if (tid < o) { rs[tid] += rs[tid + o]; rq[tid] += rq[tid + o]; }
        __syncthreads();
    }
    float mean = rs[0] * (1.0f / EE);
    float var  = rq[0] * (1.0f / EE) - mean * mean;
    float inv  = rsqrtf(var + 1e-5f);

    float4 gm = reinterpret_cast<const float4*>(gamma)[tid];
    float4 bt = reinterpret_cast<const float4*>(beta)[tid];
    float o0 = (v.x - mean) * inv * gm.x + bt.x;
    float o1 = (v.y - mean) * inv * gm.y + bt.y;
    float o2 = (v.z - mean) * inv * gm.z + bt.z;
    float o3 = (v.w - mean) * inv * gm.w + bt.w;
    yr[2 * tid]     = __floats2half2_rn(o0, o1);
    yr[2 * tid + 1] = __floats2half2_rn(o2, o3);
}

// ---------------- convert all 3 weight matrices fp32 -> fp16, one launch ----
__global__ void cvtw_all_kernel(const float4* __restrict__ wp,
                                const float4* __restrict__ w1,
                                const float4* __restrict__ w2,
                                __half2* __restrict__ op,
                                __half2* __restrict__ o1,
                                __half2* __restrict__ o2)
{
    const int n_p = EE * EE / 4;
    const int n_1 = EE * DFF / 4;
    const int n_2 = DFF * EE / 4;
    int i = blockIdx.x * blockDim.x + threadIdx.x;
    const float4* in; __half2* out; int j;
    if (i < n_p)            { in = wp; out = op; j = i; }
    else if (i < n_p + n_1) { in = w1; out = o1; j = i - n_p; }
    else if (i < n_p + n_1 + n_2) { in = w2; out = o2; j = i - n_p - n_1; }
    else return;
    float4 v = in[j];
    out[2 * j]     = __floats2half2_rn(v.x, v.y);
    out[2 * j + 1] = __floats2half2_rn(v.z, v.w);
}

// ---------------- pack wq/wk/wv [H,E,hd] -> fp16 [E, 3E] ----------------
__global__ void pack_w_kernel(const float* __restrict__ wq,
                              const float* __restrict__ wk,
                              const float* __restrict__ wv,
                              __half* __restrict__ out)
{
    int idx = blockIdx.x * blockDim.x + threadIdx.x;
    const int total = 3 * EE * EE;
    if (idx >= total) return;
    int part = idx / (EE * EE);
    int rem  = idx % (EE * EE);
    int e = rem / EE;
    int c = rem % EE;
    const float* w = (part == 0) ? wq : (part == 1) ? wk : wv;
    out[(size_t)e * (3 * EE) + part * EE + c] =
        __float2half(w[(size_t)(c >> 6) * (EE * HD) + (size_t)e * HD + (c & 63)]);
}

// ---------------- fp16 GEMM: 128x128x32, 3-stage ring, 1 sync/iter ----------
// 8 warps (4x2), warp tile 32x64 via m16n8k16. Residual (EPI==3) is fp16.
#define MM_SMEM3 ((3*128*40 + 3*32*136) * 2)   // 56832 B dynamic

template <int EPI, bool HOUT>
__global__ void __launch_bounds__(256, 2)
mm_fp16(const __half* __restrict__ A,
        const __half* __restrict__ B,
        const float* __restrict__ bias,
        const __half* __restrict__ res,
        void* __restrict__ Cout,
        int M, int N, int K)
{
    extern __shared__ __half smh[];
    __half (*As)[128][40] = reinterpret_cast<__half(*)[128][40]>(smh);
    __half (*Bs)[32][136] = reinterpret_cast<__half(*)[32][136]>(smh + 3 * 128 * 40);

    int tid = threadIdx.x;
    int lane = tid & 31, wid = tid >> 5;
    int wm = wid >> 1, wn = wid & 1;
    int g = lane >> 2, c = lane & 3;
    int rowBase = blockIdx.y * 128;
    int colBase = blockIdx.x * 128;

    float acc[2][8][4];
    #pragma unroll
    for (int i = 0; i < 2; i++)
        #pragma unroll
        for (int j = 0; j < 8; j++)
            #pragma unroll
            for (int k = 0; k < 4; k++) acc[i][j][k] = 0.f;

    auto load_stage = [&](int buf, int kk) {
        #pragma unroll
        for (int i = 0; i < 2; i++) {
            int idx = i * 256 + tid;
            int m = idx >> 2, ch = idx & 3;
            cp16(&As[buf][m][ch * 8], A + (size_t)(rowBase + m) * K + kk + ch * 8);
        }
        #pragma unroll
        for (int i = 0; i < 2; i++) {
            int idx = i * 256 + tid;
            int r = idx >> 4, ch = idx & 15;
            cp16(&Bs[buf][r][ch * 8], B + (size_t)(kk + r) * N + colBase + ch * 8);
        }
        cp_commit();
    };

    int nk = K / 32;
    load_stage(0, 0);
    load_stage(1, 32);

    int cur = 0;
    for (int k0 = 0; k0 < nk; k0++) {
        cp_wait<1>();
        __syncthreads();
        if (k0 + 2 < nk) load_stage((k0 + 2) % 3, (k0 + 2) * 32);
        else             cp_commit();

        #pragma unroll
        for (int ks = 0; ks < 2; ks++) {
            int kb = ks * 16;
            uint32_t af[2][4];
            #pragma unroll
            for (int mt = 0; mt < 2; mt++) {
                int m0 = wm * 32 + mt * 16;
                ldsm_x4(af[mt], &As[cur][m0 + (lane & 15)][kb + ((lane >> 4) << 3)]);
            }
            uint32_t bf[8][2];
            #pragma unroll
            for (int np = 0; np < 4; np++) {
                int n0 = wn * 64 + np * 16;
                uint32_t q[4];
                ldsm_x4t(q, &Bs[cur][kb + (lane & 15)][n0 + ((lane >> 4) << 3)]);
                bf[2*np][0]   = q[0]; bf[2*np][1]   = q[1];
                bf[2*np+1][0] = q[2]; bf[2*np+1][1] = q[3];
            }
            #pragma unroll
            for (int mt = 0; mt < 2; mt++)
                #pragma unroll
                for (int nt = 0; nt < 8; nt++)
                    mma_f16(acc[mt][nt], af[mt], bf[nt]);
        }
        cur = (cur == 2) ? 0 : cur + 1;
    }

    #pragma unroll
    for (int mt = 0; mt < 2; mt++) {
        int row0 = rowBase + wm * 32 + mt * 16 + g;
        #pragma unroll
        for (int nt = 0; nt < 8; nt++) {
            int col = colBase + wn * 64 + nt * 8 + c * 2;
            float v0 = acc[mt][nt][0], v1 = acc[mt][nt][1];
            float v2 = acc[mt][nt][2], v3 = acc[mt][nt][3];
            if (EPI >= 1) {
                float b0 = bias[col], b1 = bias[col + 1];
                v0 += b0; v1 += b1; v2 += b0; v3 += b1;
            }
            if (EPI == 2) {
                v0 = fmaxf(v0, 0.f); v1 = fmaxf(v1, 0.f);
                v2 = fmaxf(v2, 0.f); v3 = fmaxf(v3, 0.f);
            }
            if (EPI == 3) {
                float2 r0 = __half22float2(*reinterpret_cast<const __half2*>(&res[(size_t)row0 * N + col]));
                float2 r1 = __half22float2(*reinterpret_cast<const __half2*>(&res[(size_t)(row0 + 8) * N + col]));
                v0 += r0.x; v1 += r0.y; v2 += r1.x; v3 += r1.y;
            }
            if (HOUT) {
                __half* Ch = (__half*)Cout;
                *reinterpret_cast<__half2*>(&Ch[(size_t)row0 * N + col])       = __floats2half2_rn(v0, v1);
                *reinterpret_cast<__half2*>(&Ch[(size_t)(row0 + 8) * N + col]) = __floats2half2_rn(v2, v3);
            } else {
                float* Cf = (float*)Cout;
                *reinterpret_cast<float2*>(&Cf[(size_t)row0 * N + col])       = make_float2(v0, v1);
                *reinterpret_cast<float2*>(&Cf[(size_t)(row0 + 8) * N + col]) = make_float2(v2, v3);
            }
        }
    }
}

// ---------------- fused flash attention (R8/R11, unchanged) ----------
__global__ void __launch_bounds__(128)
flash_kernel(const __half* __restrict__ qkv, __half* __restrict__ o)
{
    __shared__ __half KP[2][64][72];
    __shared__ __half Vs[2][64][72];

    int bh = blockIdx.y;
    int b = bh >> 4, h = bh & 15;
    int rt = gridDim.x - 1 - blockIdx.x;
    int q0 = rt * 64;

    int tid = threadIdx.x;
    int lane = tid & 31, wid = tid >> 5;
    int g = lane >> 2, c = lane & 3;
    int wbase = wid * 16;
    const int S3E = 3 * EE;

    auto load_tile = [&](int buf, int st) {
        const __half* Kg = qkv + (size_t)(b * TT + st * 64) * S3E + EE + h * HD;
        const __half* Vg = Kg + EE;
        #pragma unroll
        for (int i = 0; i < 4; i++) {
            int idx = i * 128 + tid;
            int r = idx >> 3, ch = idx & 7;
            cp16(&KP[buf][r][ch * 8], Kg + (size_t)r * S3E + ch * 8);
            cp16(&Vs[buf][r][ch * 8], Vg + (size_t)r * S3E + ch * 8);
        }
        cp_commit();
    };

    load_tile(0, 0);

    uint32_t qf[4][4];
    {
        const __half* Qb = qkv + (size_t)(b * TT + q0 + wbase) * S3E + h * HD;
        const float qs = 0.125f * 1.4426950408889634f;
        const __half2 sc = __floats2half2_rn(qs, qs);
        #pragma unroll
        for (int ks = 0; ks < 4; ks++) {
            int kb = ks * 16;
            __half2 t0 = __hmul2(*(const __half2*)(Qb + (size_t)g       * S3E + kb + 2 * c),     sc);
            __half2 t1 = __hmul2(*(const __half2*)(Qb + (size_t)(g + 8) * S3E + kb + 2 * c),     sc);
            __half2 t2 = __hmul2(*(const __half2*)(Qb + (size_t)g       * S3E + kb + 2 * c + 8), sc);
            __half2 t3 = __hmul2(*(const __half2*)(Qb + (size_t)(g + 8) * S3E + kb + 2 * c + 8), sc);
            qf[ks][0] = *reinterpret_cast<uint32_t*>(&t0);
            qf[ks][1] = *reinterpret_cast<uint32_t*>(&t1);
            qf[ks][2] = *reinterpret_cast<uint32_t*>(&t2);
            qf[ks][3] = *reinterpret_cast<uint32_t*>(&t3);
        }
    }

    float m0 = -INFINITY, m1 = -INFINITY, l0 = 0.f, l1 = 0.f;
    float oacc[8][4];
    #pragma unroll
    for (int nt = 0; nt < 8; nt++)
        #pragma unroll
        for (int k = 0; k < 4; k++) oacc[nt][k] = 0.f;

    for (int st = 0; st <= rt; st++) {
        int cur = st & 1;

        __syncthreads();
        if (st + 1 <= rt) { load_tile(cur ^ 1, st + 1); cp_wait<1>(); }
        else              { cp_wait<0>(); }
        __syncthreads();

        float sacc[8][4];
        #pragma unroll
        for (int nt = 0; nt < 8; nt++)
            #pragma unroll
            for (int k = 0; k < 4; k++) sacc[nt][k] = 0.f;

        #pragma unroll
        for (int ks = 0; ks < 4; ks++) {
            int kb = ks * 16;
            #pragma unroll
            for (int np = 0; np < 4; np++) {
                uint32_t q[4];
                ldsm_x4(q, &KP[cur][np * 16 + (lane & 7) + ((lane & 16) >> 1)][kb + (lane & 8)]);
                uint32_t b0[2] = {q[0], q[1]}, b1[2] = {q[2], q[3]};
                mma_f16(sacc[2 * np],     qf[ks], b0);
                mma_f16(sacc[2 * np + 1], qf[ks], b1);
            }
        }

        if (st == rt) {
            int ql0 = wbase + g, ql1 = ql0 + 8;
            #pragma unroll
            for (int nt = 0; nt < 8; nt++) {
                int kl = nt * 8 + 2 * c;
                if (kl     > ql0) sacc[nt][0] = -1e30f;
                if (kl + 1 > ql0) sacc[nt][1] = -1e30f;
                if (kl     > ql1) sacc[nt][2] = -1e30f;
                if (kl + 1 > ql1) sacc[nt][3] = -1e30f;
            }
        }

        float mx0 = -1e30f, mx1 = -1e30f;
        #pragma unroll
        for (int nt = 0; nt < 8; nt++) {
            mx0 = fmaxf(mx0, fmaxf(sacc[nt][0], sacc[nt][1]));
            mx1 = fmaxf(mx1, fmaxf(sacc[nt][2], sacc[nt][3]));
        }
        mx0 = fmaxf(mx0, __shfl_xor_sync(0xffffffffu, mx0, 1));
        mx0 = fmaxf(mx0, __shfl_xor_sync(0xffffffffu, mx0, 2));
        mx1 = fmaxf(mx1, __shfl_xor_sync(0xffffffffu, mx1, 1));
        mx1 = fmaxf(mx1, __shfl_xor_sync(0xffffffffu, mx1, 2));

        float mn0 = fmaxf(m0, mx0), mn1 = fmaxf(m1, mx1);
        float al0 = ex2(m0 - mn0), al1 = ex2(m1 - mn1);
        m0 = mn0; m1 = mn1;

        float rs0 = 0.f, rs1 = 0.f;
        #pragma unroll
        for (int nt = 0; nt < 8; nt++) {
            float p0 = ex2(sacc[nt][0] - m0);
            float p1 = ex2(sacc[nt][1] - m0);
            float p2 = ex2(sacc[nt][2] - m1);
            float p3 = ex2(sacc[nt][3] - m1);
            sacc[nt][0] = p0; sacc[nt][1] = p1; sacc[nt][2] = p2; sacc[nt][3] = p3;
            rs0 += p0 + p1; rs1 += p2 + p3;
        }
        rs0 += __shfl_xor_sync(0xffffffffu, rs0, 1);
        rs0 += __shfl_xor_sync(0xffffffffu, rs0, 2);
        rs1 += __shfl_xor_sync(0xffffffffu, rs1, 1);
        rs1 += __shfl_xor_sync(0xffffffffu, rs1, 2);
        l0 = l0 * al0 + rs0;
        l1 = l1 * al1 + rs1;

        #pragma unroll
        for (int nt = 0; nt < 8; nt++) {
            oacc[nt][0] *= al0; oacc[nt][1] *= al0;
            oacc[nt][2] *= al1; oacc[nt][3] *= al1;
        }

        __syncthreads();
        #pragma unroll
        for (int nt = 0; nt < 8; nt++) {
            int col = nt * 8 + 2 * c;
            *reinterpret_cast<__half2*>(&KP[cur][wbase + g    ][col]) = __floats2half2_rn(sacc[nt][0], sacc[nt][1]);
            *reinterpret_cast<__half2*>(&KP[cur][wbase + g + 8][col]) = __floats2half2_rn(sacc[nt][2], sacc[nt][3]);
        }
        __syncwarp();

        #pragma unroll
        for (int ks = 0; ks < 4; ks++) {
            int kb = ks * 16;
            uint32_t af[4];
            ldsm_x4(af, &KP[cur][wbase + (lane & 15)][kb + ((lane >> 4) << 3)]);
            #pragma unroll
            for (int np = 0; np < 4; np++) {
                uint32_t q[4];
                ldsm_x4t(q, &Vs[cur][kb + (lane & 15)][np * 16 + ((lane >> 4) << 3)]);
                uint32_t b0[2] = {q[0], q[1]}, b1[2] = {q[2], q[3]};
                mma_f16(oacc[2 * np],     af, b0);
                mma_f16(oacc[2 * np + 1], af, b1);
            }
        }
    }

    float i0 = 1.0f / l0, i1 = 1.0f / l1;
    __half* Ob = o + (size_t)(b * TT + q0 + wbase) * EE + h * HD;
    #pragma unroll
    for (int nt = 0; nt < 8; nt++) {
        int col = nt * 8 + 2 * c;
        *reinterpret_cast<__half2*>(&Ob[(size_t)g * EE + col]) =
            __floats2half2_rn(oacc[nt][0] * i0, oacc[nt][1] * i0);
        *reinterpret_cast<__half2*>(&Ob[(size_t)(g + 8) * EE + col]) =
            __floats2half2_rn(oacc[nt][2] * i1, oacc[nt][3] * i1);
    }
}

// ---------------- launcher ----------------
extern "C" void kernel_launch(void* const* d_in, const int* in_sizes, int n_in,
                              void* d_out, int out_size)
{
    const float* x      = (const float*)d_in[0];
    const float* wq     = (const float*)d_in[1];
    const float* wk     = (const float*)d_in[2];
    const float* wv     = (const float*)d_in[3];
    const float* w_proj = (const float*)d_in[4];
    const float* b_proj = (const float*)d_in[5];
    const float* gamma1 = (const float*)d_in[6];
    const float* beta1  = (const float*)d_in[7];
    const float* gamma2 = (const float*)d_in[8];
    const float* beta2  = (const float*)d_in[9];
    const float* w1     = (const float*)d_in[10];
    const float* b1     = (const float*)d_in[11];
    const float* w2     = (const float*)d_in[12];
    const float* b2     = (const float*)d_in[13];
    float* out = (float*)d_out;

    float *p_x2;
    __half *p_hh, *p_wqkv, *p_qkv, *p_o, *p_h2h, *p_ffn, *p_wp, *p_w1, *p_w2;
    cudaGetSymbolAddress((void**)&p_hh,   g_hh);
    cudaGetSymbolAddress((void**)&p_wqkv, g_wqkv);
    cudaGetSymbolAddress((void**)&p_qkv,  g_qkv);
    cudaGetSymbolAddress((void**)&p_o,    g_o);
    cudaGetSymbolAddress((void**)&p_x2,   g_x2);
    cudaGetSymbolAddress((void**)&p_h2h,  g_h2h);
    cudaGetSymbolAddress((void**)&p_ffn,  g_ffn);
    cudaGetSymbolAddress((void**)&p_wp,   g_wp);
    cudaGetSymbolAddress((void**)&p_w1,   g_w1);
    cudaGetSymbolAddress((void**)&p_w2,   g_w2);

    cudaFuncSetAttribute(mm_fp16<0, true>,  cudaFuncAttributeMaxDynamicSharedMemorySize, MM_SMEM3);
    cudaFuncSetAttribute(mm_fp16<2, true>,  cudaFuncAttributeMaxDynamicSharedMemorySize, MM_SMEM3);
    cudaFuncSetAttribute(mm_fp16<3, false>, cudaFuncAttributeMaxDynamicSharedMemorySize, MM_SMEM3);

    const int CVT_TOTAL4 = (EE * EE + EE * DFF + DFF * EE) / 4;

    // 1) LN1 (fp16 out, single pass)
    ln_kernel<<<NTOK, 256>>>(x, gamma1, beta1, p_hh);
    // 2) pack qkv weights + convert all other weights (one launch)
    pack_w_kernel<<<(3 * EE * EE) / 256, 256>>>(wq, wk, wv, p_wqkv);
    cvtw_all_kernel<<<(CVT_TOTAL4 + 255) / 256, 256>>>(
        (const float4*)w_proj, (const float4*)w1, (const float4*)w2,
        (__half2*)p_wp, (__half2*)p_w1, (__half2*)p_w2);
    // 3) QKV = h @ Wqkv (fp16 out)
    mm_fp16<0, true><<<dim3(3 * EE / 128, NTOK / 128), 256, MM_SMEM3>>>(p_hh, p_wqkv, nullptr, nullptr, p_qkv, NTOK, 3 * EE, EE);
    // 4-6) fused flash attention (fp16)
    flash_kernel<<<dim3(TT / 64, BHN), 128>>>(p_qkv, p_o);
    // 7) x2 = h + O @ w_proj + b_proj (fp32 out, fp16 residual)
    mm_fp16<3, false><<<dim3(EE / 128, NTOK / 128), 256, MM_SMEM3>>>(p_o, p_wp, b_proj, p_hh, p_x2, NTOK, EE, EE);
    // 8) LN2 (fp16 out, single pass)
    ln_kernel<<<NTOK, 256>>>(p_x2, gamma2, beta2, p_h2h);
    // 9) ffn = relu(h2 @ w1 + b1) (fp16 out)
    mm_fp16<2, true><<<dim3(DFF / 128, NTOK / 128), 256, MM_SMEM3>>>(p_h2h, p_w1, b1, nullptr, p_ffn, NTOK, DFF, EE);
    // 10) out = h2 + ffn @ w2 + b2 (fp32 out, fp16 residual)
    mm_fp16<3, false><<<dim3(EE / 128, NTOK / 128), 256, MM_SMEM3>>>(p_ffn, p_w2, b2, p_h2h, out, NTOK, EE, DFF);
}

// round 14
// speedup vs baseline: 1.2637x; 1.0653x over previous
#include <cuda_runtime.h>
#include <cuda_fp16.h>
#include <math.h>
#include <stdint.h>

// Problem constants
#define BB 2
#define TT 2048
#define EE 1024
#define HH 16
#define HD 64
#define DFF 4096
#define NTOK (BB*TT)          // 4096
#define BHN (BB*HH)           // 32

// ---------------- scratch (device globals) ----------------
__device__ __half g_hh  [NTOK*EE];     // LN1 fp16 (GEMM A + residual)
__device__ __half g_wqkv[EE*3*EE];     // packed fp16 [E,3E]
__device__ __half g_qkv [NTOK*3*EE];   // fp16
__device__ __half g_o   [NTOK*EE];     // fp16
__device__ float  g_x2  [NTOK*EE];     // fp32 (LN2 input)
__device__ __half g_h2h [NTOK*EE];     // LN2 fp16 (GEMM A + residual)
__device__ __half g_ffn [NTOK*DFF];    // fp16
__device__ __half g_wp  [EE*EE];
__device__ __half g_w1  [EE*DFF];
__device__ __half g_w2  [DFF*EE];

// ---------------- helpers ----------------
__device__ __forceinline__ void cp16(void* s, const void* g) {
    uint32_t sa = (uint32_t)__cvta_generic_to_shared(s);
    asm volatile("cp.async.cg.shared.global [%0], [%1], 16;" :: "r"(sa), "l"(g));
}
__device__ __forceinline__ void cp_commit() { asm volatile("cp.async.commit_group;"); }
template<int N> __device__ __forceinline__ void cp_wait() {
    asm volatile("cp.async.wait_group %0;" :: "n"(N));
}
__device__ __forceinline__ void ldsm_x4(uint32_t r[4], const void* p) {
    uint32_t a = (uint32_t)__cvta_generic_to_shared(p);
    asm volatile("ldmatrix.sync.aligned.m8n8.x4.shared.b16 {%0,%1,%2,%3}, [%4];"
        : "=r"(r[0]), "=r"(r[1]), "=r"(r[2]), "=r"(r[3]) : "r"(a));
}
__device__ __forceinline__ void ldsm_x4t(uint32_t r[4], const void* p) {
    uint32_t a = (uint32_t)__cvta_generic_to_shared(p);
    asm volatile("ldmatrix.sync.aligned.m8n8.x4.trans.shared.b16 {%0,%1,%2,%3}, [%4];"
        : "=r"(r[0]), "=r"(r[1]), "=r"(r[2]), "=r"(r[3]) : "r"(a));
}
__device__ __forceinline__ void mma_f16(float acc[4], const uint32_t a[4], const uint32_t b[2]) {
    asm volatile(
        "mma.sync.aligned.m16n8k16.row.col.f32.f16.f16.f32 "
        "{%0,%1,%2,%3},{%4,%5,%6,%7},{%8,%9},{%0,%1,%2,%3};"
        : "+f"(acc[0]), "+f"(acc[1]), "+f"(acc[2]), "+f"(acc[3])
        : "r"(a[0]), "r"(a[1]), "r"(a[2]), "r"(a[3]), "r"(b[0]), "r"(b[1]));
}
__device__ __forceinline__ float ex2(float x) {
    float r;
    asm("ex2.approx.ftz.f32 %0, %1;" : "=f"(r) : "f"(x));
    return r;
}

// ---------------- LayerNorm: single pass, fp16 output ----------------
__global__ void ln_kernel(const float* __restrict__ x,
                          const float* __restrict__ gamma,
                          const float* __restrict__ beta,
                          __half* __restrict__ yh)
{
    int row = blockIdx.x;
    int tid = threadIdx.x;
    const float4* xr = reinterpret_cast<const float4*>(x + (size_t)row * EE);
    __half2* yr = reinterpret_cast<__half2*>(yh + (size_t)row * EE);
    __shared__ float rs[256], rq[256];

    float4 v = xr[tid];
    float s  = v.x + v.y + v.z + v.w;
    float q  = v.x * v.x + v.y * v.y + v.z * v.z + v.w * v.w;
    rs[tid] = s; rq[tid] = q;
    __syncthreads();
    for (int o = 128; o > 0; o >>= 1) {
        if (tid < o) { rs[tid] += rs[tid + o]; rq[tid] += rq[tid + o]; }
        __syncthreads();
    }
    float mean = rs[0] * (1.0f / EE);
    float var  = rq[0] * (1.0f / EE) - mean * mean;
    float inv  = rsqrtf(var + 1e-5f);

    float4 gm = reinterpret_cast<const float4*>(gamma)[tid];
    float4 bt = reinterpret_cast<const float4*>(beta)[tid];
    float o0 = (v.x - mean) * inv * gm.x + bt.x;
    float o1 = (v.y - mean) * inv * gm.y + bt.y;
    float o2 = (v.z - mean) * inv * gm.z + bt.z;
    float o3 = (v.w - mean) * inv * gm.w + bt.w;
    yr[2 * tid]     = __floats2half2_rn(o0, o1);
    yr[2 * tid + 1] = __floats2half2_rn(o2, o3);
}

// ---------------- convert all 3 weight matrices fp32 -> fp16 ----------------
__global__ void cvtw_all_kernel(const float4* __restrict__ wp,
                                const float4* __restrict__ w1,
                                const float4* __restrict__ w2,
                                __half2* __restrict__ op,
                                __half2* __restrict__ o1,
                                __half2* __restrict__ o2)
{
    const int n_p = EE * EE / 4;
    const int n_1 = EE * DFF / 4;
    const int n_2 = DFF * EE / 4;
    int i = blockIdx.x * blockDim.x + threadIdx.x;
    const float4* in; __half2* out; int j;
    if (i < n_p)            { in = wp; out = op; j = i; }
    else if (i < n_p + n_1) { in = w1; out = o1; j = i - n_p; }
    else if (i < n_p + n_1 + n_2) { in = w2; out = o2; j = i - n_p - n_1; }
    else return;
    float4 v = in[j];
    out[2 * j]     = __floats2half2_rn(v.x, v.y);
    out[2 * j + 1] = __floats2half2_rn(v.z, v.w);
}

// ---------------- pack wq/wk/wv [H,E,hd] -> fp16 [E, 3E] ----------------
__global__ void pack_w_kernel(const float* __restrict__ wq,
                              const float* __restrict__ wk,
                              const float* __restrict__ wv,
                              __half* __restrict__ out)
{
    int idx = blockIdx.x * blockDim.x + threadIdx.x;
    const int total = 3 * EE * EE;
    if (idx >= total) return;
    int part = idx / (EE * EE);
    int rem  = idx % (EE * EE);
    int e = rem / EE;
    int c = rem % EE;
    const float* w = (part == 0) ? wq : (part == 1) ? wk : wv;
    out[(size_t)e * (3 * EE) + part * EE + c] =
        __float2half(w[(size_t)(c >> 6) * (EE * HD) + (size_t)e * HD + (c & 63)]);
}

// ---------------- fp16 GEMM: 128x128x32, 4 warps, warp tile 64x64 -----------
// 3-stage ring, 1 sync/iter. Residual (EPI==3) is fp16.
#define MM_SMEM3 ((3*128*40 + 3*32*136) * 2)   // 56832 B dynamic

template <int EPI, bool HOUT>
__global__ void __launch_bounds__(128, 2)
mm_fp16(const __half* __restrict__ A,
        const __half* __restrict__ B,
        const float* __restrict__ bias,
        const __half* __restrict__ res,
        void* __restrict__ Cout,
        int M, int N, int K)
{
    extern __shared__ __half smh[];
    __half (*As)[128][40] = reinterpret_cast<__half(*)[128][40]>(smh);
    __half (*Bs)[32][136] = reinterpret_cast<__half(*)[32][136]>(smh + 3 * 128 * 40);

    int tid = threadIdx.x;
    int lane = tid & 31, wid = tid >> 5;   // 4 warps
    int wm = wid >> 1, wn = wid & 1;       // 2 x 2 warp grid, warp tile 64x64
    int g = lane >> 2, c = lane & 3;
    int rowBase = blockIdx.y * 128;
    int colBase = blockIdx.x * 128;

    float acc[4][8][4];
    #pragma unroll
    for (int i = 0; i < 4; i++)
        #pragma unroll
        for (int j = 0; j < 8; j++)
            #pragma unroll
            for (int k = 0; k < 4; k++) acc[i][j][k] = 0.f;

    auto load_stage = [&](int buf, int kk) {
        // A: 128x32 fp16 = 512 chunks, 4 per thread
        #pragma unroll
        for (int i = 0; i < 4; i++) {
            int idx = i * 128 + tid;
            int m = idx >> 2, ch = idx & 3;
            cp16(&As[buf][m][ch * 8], A + (size_t)(rowBase + m) * K + kk + ch * 8);
        }
        // B: 32x128 fp16 = 512 chunks, 4 per thread
        #pragma unroll
        for (int i = 0; i < 4; i++) {
            int idx = i * 128 + tid;
            int r = idx >> 4, ch = idx & 15;
            cp16(&Bs[buf][r][ch * 8], B + (size_t)(kk + r) * N + colBase + ch * 8);
        }
        cp_commit();
    };

    int nk = K / 32;
    load_stage(0, 0);
    load_stage(1, 32);

    int cur = 0;
    for (int k0 = 0; k0 < nk; k0++) {
        cp_wait<1>();            // stage k0 resident
        __syncthreads();         // buffer (k0+2)%3 free
        if (k0 + 2 < nk) load_stage((k0 + 2) % 3, (k0 + 2) * 32);
        else             cp_commit();

        #pragma unroll
        for (int ks = 0; ks < 2; ks++) {
            int kb = ks * 16;
            uint32_t af[4][4];
            #pragma unroll
            for (int mt = 0; mt < 4; mt++) {
                int m0 = wm * 64 + mt * 16;
                ldsm_x4(af[mt], &As[cur][m0 + (lane & 15)][kb + ((lane >> 4) << 3)]);
            }
            uint32_t bf[8][2];
            #pragma unroll
            for (int np = 0; np < 4; np++) {
                int n0 = wn * 64 + np * 16;
                uint32_t q[4];
                ldsm_x4t(q, &Bs[cur][kb + (lane & 15)][n0 + ((lane >> 4) << 3)]);
                bf[2*np][0]   = q[0]; bf[2*np][1]   = q[1];
                bf[2*np+1][0] = q[2]; bf[2*np+1][1] = q[3];
            }
            #pragma unroll
            for (int mt = 0; mt < 4; mt++)
                #pragma unroll
                for (int nt = 0; nt < 8; nt++)
                    mma_f16(acc[mt][nt], af[mt], bf[nt]);
        }
        cur = (cur == 2) ? 0 : cur + 1;
    }

    #pragma unroll
    for (int mt = 0; mt < 4; mt++) {
        int row0 = rowBase + wm * 64 + mt * 16 + g;
        #pragma unroll
        for (int nt = 0; nt < 8; nt++) {
            int col = colBase + wn * 64 + nt * 8 + c * 2;
            float v0 = acc[mt][nt][0], v1 = acc[mt][nt][1];
            float v2 = acc[mt][nt][2], v3 = acc[mt][nt][3];
            if (EPI >= 1) {
                float b0 = bias[col], b1 = bias[col + 1];
                v0 += b0; v1 += b1; v2 += b0; v3 += b1;
            }
            if (EPI == 2) {
                v0 = fmaxf(v0, 0.f); v1 = fmaxf(v1, 0.f);
                v2 = fmaxf(v2, 0.f); v3 = fmaxf(v3, 0.f);
            }
            if (EPI == 3) {
                float2 r0 = __half22float2(*reinterpret_cast<const __half2*>(&res[(size_t)row0 * N + col]));
                float2 r1 = __half22float2(*reinterpret_cast<const __half2*>(&res[(size_t)(row0 + 8) * N + col]));
                v0 += r0.x; v1 += r0.y; v2 += r1.x; v3 += r1.y;
            }
            if (HOUT) {
                __half* Ch = (__half*)Cout;
                *reinterpret_cast<__half2*>(&Ch[(size_t)row0 * N + col])       = __floats2half2_rn(v0, v1);
                *reinterpret_cast<__half2*>(&Ch[(size_t)(row0 + 8) * N + col]) = __floats2half2_rn(v2, v3);
            } else {
                float* Cf = (float*)Cout;
                *reinterpret_cast<float2*>(&Cf[(size_t)row0 * N + col])       = make_float2(v0, v1);
                *reinterpret_cast<float2*>(&Cf[(size_t)(row0 + 8) * N + col]) = make_float2(v2, v3);
            }
        }
    }
}

// ---------------- fused flash attention (unchanged) ----------
__global__ void __launch_bounds__(128)
flash_kernel(const __half* __restrict__ qkv, __half* __restrict__ o)
{
    __shared__ __half KP[2][64][72];
    __shared__ __half Vs[2][64][72];

    int bh = blockIdx.y;
    int b = bh >> 4, h = bh & 15;
    int rt = gridDim.x - 1 - blockIdx.x;
    int q0 = rt * 64;

    int tid = threadIdx.x;
    int lane = tid & 31, wid = tid >> 5;
    int g = lane >> 2, c = lane & 3;
    int wbase = wid * 16;
    const int S3E = 3 * EE;

    auto load_tile = [&](int buf, int st) {
        const __half* Kg = qkv + (size_t)(b * TT + st * 64) * S3E + EE + h * HD;
        const __half* Vg = Kg + EE;
        #pragma unroll
        for (int i = 0; i < 4; i++) {
            int idx = i * 128 + tid;
            int r = idx >> 3, ch = idx & 7;
            cp16(&KP[buf][r][ch * 8], Kg + (size_t)r * S3E + ch * 8);
            cp16(&Vs[buf][r][ch * 8], Vg + (size_t)r * S3E + ch * 8);
        }
        cp_commit();
    };

    load_tile(0, 0);

    uint32_t qf[4][4];
    {
        const __half* Qb = qkv + (size_t)(b * TT + q0 + wbase) * S3E + h * HD;
        const float qs = 0.125f * 1.4426950408889634f;
        const __half2 sc = __floats2half2_rn(qs, qs);
        #pragma unroll
        for (int ks = 0; ks < 4; ks++) {
            int kb = ks * 16;
            __half2 t0 = __hmul2(*(const __half2*)(Qb + (size_t)g       * S3E + kb + 2 * c),     sc);
            __half2 t1 = __hmul2(*(const __half2*)(Qb + (size_t)(g + 8) * S3E + kb + 2 * c),     sc);
            __half2 t2 = __hmul2(*(const __half2*)(Qb + (size_t)g       * S3E + kb + 2 * c + 8), sc);
            __half2 t3 = __hmul2(*(const __half2*)(Qb + (size_t)(g + 8) * S3E + kb + 2 * c + 8), sc);
            qf[ks][0] = *reinterpret_cast<uint32_t*>(&t0);
            qf[ks][1] = *reinterpret_cast<uint32_t*>(&t1);
            qf[ks][2] = *reinterpret_cast<uint32_t*>(&t2);
            qf[ks][3] = *reinterpret_cast<uint32_t*>(&t3);
        }
    }

    float m0 = -INFINITY, m1 = -INFINITY, l0 = 0.f, l1 = 0.f;
    float oacc[8][4];
    #pragma unroll
    for (int nt = 0; nt < 8; nt++)
        #pragma unroll
        for (int k = 0; k < 4; k++) oacc[nt][k] = 0.f;

    for (int st = 0; st <= rt; st++) {
        int cur = st & 1;

        __syncthreads();
        if (st + 1 <= rt) { load_tile(cur ^ 1, st + 1); cp_wait<1>(); }
        else              { cp_wait<0>(); }
        __syncthreads();

        float sacc[8][4];
        #pragma unroll
        for (int nt = 0; nt < 8; nt++)
            #pragma unroll
            for (int k = 0; k < 4; k++) sacc[nt][k] = 0.f;

        #pragma unroll
        for (int ks = 0; ks < 4; ks++) {
            int kb = ks * 16;
            #pragma unroll
            for (int np = 0; np < 4; np++) {
                uint32_t q[4];
                ldsm_x4(q, &KP[cur][np * 16 + (lane & 7) + ((lane & 16) >> 1)][kb + (lane & 8)]);
                uint32_t b0[2] = {q[0], q[1]}, b1[2] = {q[2], q[3]};
                mma_f16(sacc[2 * np],     qf[ks], b0);
                mma_f16(sacc[2 * np + 1], qf[ks], b1);
            }
        }

        if (st == rt) {
            int ql0 = wbase + g, ql1 = ql0 + 8;
            #pragma unroll
            for (int nt = 0; nt < 8; nt++) {
                int kl = nt * 8 + 2 * c;
                if (kl     > ql0) sacc[nt][0] = -1e30f;
                if (kl + 1 > ql0) sacc[nt][1] = -1e30f;
                if (kl     > ql1) sacc[nt][2] = -1e30f;
                if (kl + 1 > ql1) sacc[nt][3] = -1e30f;
            }
        }

        float mx0 = -1e30f, mx1 = -1e30f;
        #pragma unroll
        for (int nt = 0; nt < 8; nt++) {
            mx0 = fmaxf(mx0, fmaxf(sacc[nt][0], sacc[nt][1]));
            mx1 = fmaxf(mx1, fmaxf(sacc[nt][2], sacc[nt][3]));
        }
        mx0 = fmaxf(mx0, __shfl_xor_sync(0xffffffffu, mx0, 1));
        mx0 = fmaxf(mx0, __shfl_xor_sync(0xffffffffu, mx0, 2));
        mx1 = fmaxf(mx1, __shfl_xor_sync(0xffffffffu, mx1, 1));
        mx1 = fmaxf(mx1, __shfl_xor_sync(0xffffffffu, mx1, 2));

        float mn0 = fmaxf(m0, mx0), mn1 = fmaxf(m1, mx1);
        float al0 = ex2(m0 - mn0), al1 = ex2(m1 - mn1);
        m0 = mn0; m1 = mn1;

        float rs0 = 0.f, rs1 = 0.f;
        #pragma unroll
        for (int nt = 0; nt < 8; nt++) {
            float p0 = ex2(sacc[nt][0] - m0);
            float p1 = ex2(sacc[nt][1] - m0);
            float p2 = ex2(sacc[nt][2] - m1);
            float p3 = ex2(sacc[nt][3] - m1);
            sacc[nt][0] = p0; sacc[nt][1] = p1; sacc[nt][2] = p2; sacc[nt][3] = p3;
            rs0 += p0 + p1; rs1 += p2 + p3;
        }
        rs0 += __shfl_xor_sync(0xffffffffu, rs0, 1);
        rs0 += __shfl_xor_sync(0xffffffffu, rs0, 2);
        rs1 += __shfl_xor_sync(0xffffffffu, rs1, 1);
        rs1 += __shfl_xor_sync(0xffffffffu, rs1, 2);
        l0 = l0 * al0 + rs0;
        l1 = l1 * al1 + rs1;

        #pragma unroll
        for (int nt = 0; nt < 8; nt++) {
            oacc[nt][0] *= al0; oacc[nt][1] *= al0;
            oacc[nt][2] *= al1; oacc[nt][3] *= al1;
        }

        __syncthreads();
        #pragma unroll
        for (int nt = 0; nt < 8; nt++) {
            int col = nt * 8 + 2 * c;
            *reinterpret_cast<__half2*>(&KP[cur][wbase + g    ][col]) = __floats2half2_rn(sacc[nt][0], sacc[nt][1]);
            *reinterpret_cast<__half2*>(&KP[cur][wbase + g + 8][col]) = __floats2half2_rn(sacc[nt][2], sacc[nt][3]);
        }
        __syncwarp();

        #pragma unroll
        for (int ks = 0; ks < 4; ks++) {
            int kb = ks * 16;
            uint32_t af[4];
            ldsm_x4(af, &KP[cur][wbase + (lane & 15)][kb + ((lane >> 4) << 3)]);
            #pragma unroll
            for (int np = 0; np < 4; np++) {
                uint32_t q[4];
                ldsm_x4t(q, &Vs[cur][kb + (lane & 15)][np * 16 + ((lane >> 4) << 3)]);
                uint32_t b0[2] = {q[0], q[1]}, b1[2] = {q[2], q[3]};
                mma_f16(oacc[2 * np],     af, b0);
                mma_f16(oacc[2 * np + 1], af, b1);
            }
        }
    }

    float i0 = 1.0f / l0, i1 = 1.0f / l1;
    __half* Ob = o + (size_t)(b * TT + q0 + wbase) * EE + h * HD;
    #pragma unroll
    for (int nt = 0; nt < 8; nt++) {
        int col = nt * 8 + 2 * c;
        *reinterpret_cast<__half2*>(&Ob[(size_t)g * EE + col]) =
            __floats2half2_rn(oacc[nt][0] * i0, oacc[nt][1] * i0);
        *reinterpret_cast<__half2*>(&Ob[(size_t)(g + 8) * EE + col]) =
            __floats2half2_rn(oacc[nt][2] * i1, oacc[nt][3] * i1);
    }
}

// ---------------- launcher ----------------
extern "C" void kernel_launch(void* const* d_in, const int* in_sizes, int n_in,
                              void* d_out, int out_size)
{
    const float* x      = (const float*)d_in[0];
    const float* wq     = (const float*)d_in[1];
    const float* wk     = (const float*)d_in[2];
    const float* wv     = (const float*)d_in[3];
    const float* w_proj = (const float*)d_in[4];
    const float* b_proj = (const float*)d_in[5];
    const float* gamma1 = (const float*)d_in[6];
    const float* beta1  = (const float*)d_in[7];
    const float* gamma2 = (const float*)d_in[8];
    const float* beta2  = (const float*)d_in[9];
    const float* w1     = (const float*)d_in[10];
    const float* b1     = (const float*)d_in[11];
    const float* w2     = (const float*)d_in[12];
    const float* b2     = (const float*)d_in[13];
    float* out = (float*)d_out;

    float *p_x2;
    __half *p_hh, *p_wqkv, *p_qkv, *p_o, *p_h2h, *p_ffn, *p_wp, *p_w1, *p_w2;
    cudaGetSymbolAddress((void**)&p_hh,   g_hh);
    cudaGetSymbolAddress((void**)&p_wqkv, g_wqkv);
    cudaGetSymbolAddress((void**)&p_qkv,  g_qkv);
    cudaGetSymbolAddress((void**)&p_o,    g_o);
    cudaGetSymbolAddress((void**)&p_x2,   g_x2);
    cudaGetSymbolAddress((void**)&p_h2h,  g_h2h);
    cudaGetSymbolAddress((void**)&p_ffn,  g_ffn);
    cudaGetSymbolAddress((void**)&p_wp,   g_wp);
    cudaGetSymbolAddress((void**)&p_w1,   g_w1);
    cudaGetSymbolAddress((void**)&p_w2,   g_w2);

    cudaFuncSetAttribute(mm_fp16<0, true>,  cudaFuncAttributeMaxDynamicSharedMemorySize, MM_SMEM3);
    cudaFuncSetAttribute(mm_fp16<2, true>,  cudaFuncAttributeMaxDynamicSharedMemorySize, MM_SMEM3);
    cudaFuncSetAttribute(mm_fp16<3, false>, cudaFuncAttributeMaxDynamicSharedMemorySize, MM_SMEM3);

    const int CVT_TOTAL4 = (EE * EE + EE * DFF + DFF * EE) / 4;

    // 1) LN1 (fp16 out, single pass)
    ln_kernel<<<NTOK, 256>>>(x, gamma1, beta1, p_hh);
    // 2) pack qkv weights + convert all other weights
    pack_w_kernel<<<(3 * EE * EE) / 256, 256>>>(wq, wk, wv, p_wqkv);
    cvtw_all_kernel<<<(CVT_TOTAL4 + 255) / 256, 256>>>(
        (const float4*)w_proj, (const float4*)w1, (const float4*)w2,
        (__half2*)p_wp, (__half2*)p_w1, (__half2*)p_w2);
    // 3) QKV = h @ Wqkv (fp16 out)
    mm_fp16<0, true><<<dim3(3 * EE / 128, NTOK / 128), 128, MM_SMEM3>>>(p_hh, p_wqkv, nullptr, nullptr, p_qkv, NTOK, 3 * EE, EE);
    // 4-6) fused flash attention (fp16)
    flash_kernel<<<dim3(TT / 64, BHN), 128>>>(p_qkv, p_o);
    // 7) x2 = h + O @ w_proj + b_proj (fp32 out, fp16 residual)
    mm_fp16<3, false><<<dim3(EE / 128, NTOK / 128), 128, MM_SMEM3>>>(p_o, p_wp, b_proj, p_hh, p_x2, NTOK, EE, EE);
    // 8) LN2 (fp16 out, single pass)
    ln_kernel<<<NTOK, 256>>>(p_x2, gamma2, beta2, p_h2h);
    // 9) ffn = relu(h2 @ w1 + b1) (fp16 out)
    mm_fp16<2, true><<<dim3(DFF / 128, NTOK / 128), 128, MM_SMEM3>>>(p_h2h, p_w1, b1, nullptr, p_ffn, NTOK, DFF, EE);
    // 10) out = h2 + ffn @ w2 + b2 (fp32 out, fp16 residual)
    mm_fp16<3, false><<<dim3(EE / 128, NTOK / 128), 128, MM_SMEM3>>>(p_ffn, p_w2, b2, p_h2h, out, NTOK, EE, DFF);
}

// round 15
// speedup vs baseline: 1.2667x; 1.0024x over previous
#include <cuda_runtime.h>
#include <cuda_fp16.h>
#include <math.h>
#include <stdint.h>

// Problem constants
#define BB 2
#define TT 2048
#define EE 1024
#define HH 16
#define HD 64
#define DFF 4096
#define NTOK (BB*TT)          // 4096
#define BHN (BB*HH)           // 32

// ---------------- scratch (device globals) ----------------
__device__ __half g_hh  [NTOK*EE];     // LN1 fp16 (GEMM A + residual)
__device__ __half g_wqkv[EE*3*EE];     // packed fp16 [E,3E]
__device__ __half g_qkv [NTOK*3*EE];   // fp16
__device__ __half g_o   [NTOK*EE];     // fp16
__device__ float  g_x2  [NTOK*EE];     // fp32 (LN2 input)
__device__ __half g_h2h [NTOK*EE];     // LN2 fp16 (GEMM A + residual)
__device__ __half g_ffn [NTOK*DFF];    // fp16
__device__ __half g_wp  [EE*EE];
__device__ __half g_w1  [EE*DFF];
__device__ __half g_w2  [DFF*EE];

// ---------------- helpers ----------------
__device__ __forceinline__ void cp16(void* s, const void* g) {
    uint32_t sa = (uint32_t)__cvta_generic_to_shared(s);
    asm volatile("cp.async.cg.shared.global [%0], [%1], 16;" :: "r"(sa), "l"(g));
}
__device__ __forceinline__ void cp_commit() { asm volatile("cp.async.commit_group;"); }
template<int N> __device__ __forceinline__ void cp_wait() {
    asm volatile("cp.async.wait_group %0;" :: "n"(N));
}
__device__ __forceinline__ void ldsm_x4(uint32_t r[4], const void* p) {
    uint32_t a = (uint32_t)__cvta_generic_to_shared(p);
    asm volatile("ldmatrix.sync.aligned.m8n8.x4.shared.b16 {%0,%1,%2,%3}, [%4];"
        : "=r"(r[0]), "=r"(r[1]), "=r"(r[2]), "=r"(r[3]) : "r"(a));
}
__device__ __forceinline__ void ldsm_x4t(uint32_t r[4], const void* p) {
    uint32_t a = (uint32_t)__cvta_generic_to_shared(p);
    asm volatile("ldmatrix.sync.aligned.m8n8.x4.trans.shared.b16 {%0,%1,%2,%3}, [%4];"
        : "=r"(r[0]), "=r"(r[1]), "=r"(r[2]), "=r"(r[3]) : "r"(a));
}
__device__ __forceinline__ void mma_f16(float acc[4], const uint32_t a[4], const uint32_t b[2]) {
    asm volatile(
        "mma.sync.aligned.m16n8k16.row.col.f32.f16.f16.f32 "
        "{%0,%1,%2,%3},{%4,%5,%6,%7},{%8,%9},{%0,%1,%2,%3};"
        : "+f"(acc[0]), "+f"(acc[1]), "+f"(acc[2]), "+f"(acc[3])
        : "r"(a[0]), "r"(a[1]), "r"(a[2]), "r"(a[3]), "r"(b[0]), "r"(b[1]));
}
__device__ __forceinline__ float ex2(float x) {
    float r;
    asm("ex2.approx.ftz.f32 %0, %1;" : "=f"(r) : "f"(x));
    return r;
}

// ---------------- LayerNorm: single pass, fp16 output ----------------
__global__ void ln_kernel(const float* __restrict__ x,
                          const float* __restrict__ gamma,
                          const float* __restrict__ beta,
                          __half* __restrict__ yh)
{
    int row = blockIdx.x;
    int tid = threadIdx.x;
    const float4* xr = reinterpret_cast<const float4*>(x + (size_t)row * EE);
    __half2* yr = reinterpret_cast<__half2*>(yh + (size_t)row * EE);
    __shared__ float rs[256], rq[256];

    float4 v = xr[tid];
    float s  = v.x + v.y + v.z + v.w;
    float q  = v.x * v.x + v.y * v.y + v.z * v.z + v.w * v.w;
    rs[tid] = s; rq[tid] = q;
    __syncthreads();
    for (int o = 128; o > 0; o >>= 1) {
        if (tid < o) { rs[tid] += rs[tid + o]; rq[tid] += rq[tid + o]; }
        __syncthreads();
    }
    float mean = rs[0] * (1.0f / EE);
    float var  = rq[0] * (1.0f / EE) - mean * mean;
    float inv  = rsqrtf(var + 1e-5f);

    float4 gm = reinterpret_cast<const float4*>(gamma)[tid];
    float4 bt = reinterpret_cast<const float4*>(beta)[tid];
    float o0 = (v.x - mean) * inv * gm.x + bt.x;
    float o1 = (v.y - mean) * inv * gm.y + bt.y;
    float o2 = (v.z - mean) * inv * gm.z + bt.z;
    float o3 = (v.w - mean) * inv * gm.w + bt.w;
    yr[2 * tid]     = __floats2half2_rn(o0, o1);
    yr[2 * tid + 1] = __floats2half2_rn(o2, o3);
}

// ---------------- convert all 3 weight matrices fp32 -> fp16 ----------------
__global__ void cvtw_all_kernel(const float4* __restrict__ wp,
                                const float4* __restrict__ w1,
                                const float4* __restrict__ w2,
                                __half2* __restrict__ op,
                                __half2* __restrict__ o1,
                                __half2* __restrict__ o2)
{
    const int n_p = EE * EE / 4;
    const int n_1 = EE * DFF / 4;
    const int n_2 = DFF * EE / 4;
    int i = blockIdx.x * blockDim.x + threadIdx.x;
    const float4* in; __half2* out; int j;
    if (i < n_p)            { in = wp; out = op; j = i; }
    else if (i < n_p + n_1) { in = w1; out = o1; j = i - n_p; }
    else if (i < n_p + n_1 + n_2) { in = w2; out = o2; j = i - n_p - n_1; }
    else return;
    float4 v = in[j];
    out[2 * j]     = __floats2half2_rn(v.x, v.y);
    out[2 * j + 1] = __floats2half2_rn(v.z, v.w);
}

// ---------------- pack wq/wk/wv [H,E,hd] -> fp16 [E, 3E] ----------------
__global__ void pack_w_kernel(const float* __restrict__ wq,
                              const float* __restrict__ wk,
                              const float* __restrict__ wv,
                              __half* __restrict__ out)
{
    int idx = blockIdx.x * blockDim.x + threadIdx.x;
    const int total = 3 * EE * EE;
    if (idx >= total) return;
    int part = idx / (EE * EE);
    int rem  = idx % (EE * EE);
    int e = rem / EE;
    int c = rem % EE;
    const float* w = (part == 0) ? wq : (part == 1) ? wk : wv;
    out[(size_t)e * (3 * EE) + part * EE + c] =
        __float2half(w[(size_t)(c >> 6) * (EE * HD) + (size_t)e * HD + (c & 63)]);
}

// ---------------- fp16 GEMM: 128x128x32, 4 warps, warp tile 64x64 -----------
// 3-stage ring, 1 sync/iter. A-fragments for BOTH k16 halves hoisted.
#define MM_SMEM3 ((3*128*40 + 3*32*136) * 2)   // 56832 B dynamic

template <int EPI, bool HOUT>
__global__ void __launch_bounds__(128, 2)
mm_fp16(const __half* __restrict__ A,
        const __half* __restrict__ B,
        const float* __restrict__ bias,
        const __half* __restrict__ res,
        void* __restrict__ Cout,
        int M, int N, int K)
{
    extern __shared__ __half smh[];
    __half (*As)[128][40] = reinterpret_cast<__half(*)[128][40]>(smh);
    __half (*Bs)[32][136] = reinterpret_cast<__half(*)[32][136]>(smh + 3 * 128 * 40);

    int tid = threadIdx.x;
    int lane = tid & 31, wid = tid >> 5;   // 4 warps
    int wm = wid >> 1, wn = wid & 1;       // 2 x 2 warp grid, warp tile 64x64
    int g = lane >> 2, c = lane & 3;
    int rowBase = blockIdx.y * 128;
    int colBase = blockIdx.x * 128;

    float acc[4][8][4];
    #pragma unroll
    for (int i = 0; i < 4; i++)
        #pragma unroll
        for (int j = 0; j < 8; j++)
            #pragma unroll
            for (int k = 0; k < 4; k++) acc[i][j][k] = 0.f;

    auto load_stage = [&](int buf, int kk) {
        #pragma unroll
        for (int i = 0; i < 4; i++) {
            int idx = i * 128 + tid;
            int m = idx >> 2, ch = idx & 3;
            cp16(&As[buf][m][ch * 8], A + (size_t)(rowBase + m) * K + kk + ch * 8);
        }
        #pragma unroll
        for (int i = 0; i < 4; i++) {
            int idx = i * 128 + tid;
            int r = idx >> 4, ch = idx & 15;
            cp16(&Bs[buf][r][ch * 8], B + (size_t)(kk + r) * N + colBase + ch * 8);
        }
        cp_commit();
    };

    int nk = K / 32;
    load_stage(0, 0);
    load_stage(1, 32);

    int cur = 0;
    for (int k0 = 0; k0 < nk; k0++) {
        cp_wait<1>();            // stage k0 resident
        __syncthreads();         // buffer (k0+2)%3 free
        if (k0 + 2 < nk) load_stage((k0 + 2) % 3, (k0 + 2) * 32);
        else             cp_commit();

        // hoist A fragments for BOTH k16 halves (8 LDSM in flight early)
        uint32_t af[2][4][4];
        #pragma unroll
        for (int ks = 0; ks < 2; ks++)
            #pragma unroll
            for (int mt = 0; mt < 4; mt++) {
                int m0 = wm * 64 + mt * 16;
                ldsm_x4(af[ks][mt],
                        &As[cur][m0 + (lane & 15)][ks * 16 + ((lane >> 4) << 3)]);
            }

        #pragma unroll
        for (int ks = 0; ks < 2; ks++) {
            int kb = ks * 16;
            uint32_t bf[8][2];
            #pragma unroll
            for (int np = 0; np < 4; np++) {
                int n0 = wn * 64 + np * 16;
                uint32_t q[4];
                ldsm_x4t(q, &Bs[cur][kb + (lane & 15)][n0 + ((lane >> 4) << 3)]);
                bf[2*np][0]   = q[0]; bf[2*np][1]   = q[1];
                bf[2*np+1][0] = q[2]; bf[2*np+1][1] = q[3];
            }
            #pragma unroll
            for (int mt = 0; mt < 4; mt++)
                #pragma unroll
                for (int nt = 0; nt < 8; nt++)
                    mma_f16(acc[mt][nt], af[ks][mt], bf[nt]);
        }
        cur = (cur == 2) ? 0 : cur + 1;
    }

    #pragma unroll
    for (int mt = 0; mt < 4; mt++) {
        int row0 = rowBase + wm * 64 + mt * 16 + g;
        #pragma unroll
        for (int nt = 0; nt < 8; nt++) {
            int col = colBase + wn * 64 + nt * 8 + c * 2;
            float v0 = acc[mt][nt][0], v1 = acc[mt][nt][1];
            float v2 = acc[mt][nt][2], v3 = acc[mt][nt][3];
            if (EPI >= 1) {
                float b0 = bias[col], b1 = bias[col + 1];
                v0 += b0; v1 += b1; v2 += b0; v3 += b1;
            }
            if (EPI == 2) {
                v0 = fmaxf(v0, 0.f); v1 = fmaxf(v1, 0.f);
                v2 = fmaxf(v2, 0.f); v3 = fmaxf(v3, 0.f);
            }
            if (EPI == 3) {
                float2 r0 = __half22float2(*reinterpret_cast<const __half2*>(&res[(size_t)row0 * N + col]));
                float2 r1 = __half22float2(*reinterpret_cast<const __half2*>(&res[(size_t)(row0 + 8) * N + col]));
                v0 += r0.x; v1 += r0.y; v2 += r1.x; v3 += r1.y;
            }
            if (HOUT) {
                __half* Ch = (__half*)Cout;
                *reinterpret_cast<__half2*>(&Ch[(size_t)row0 * N + col])       = __floats2half2_rn(v0, v1);
                *reinterpret_cast<__half2*>(&Ch[(size_t)(row0 + 8) * N + col]) = __floats2half2_rn(v2, v3);
            } else {
                float* Cf = (float*)Cout;
                *reinterpret_cast<float2*>(&Cf[(size_t)row0 * N + col])       = make_float2(v0, v1);
                *reinterpret_cast<float2*>(&Cf[(size_t)(row0 + 8) * N + col]) = make_float2(v2, v3);
            }
        }
    }
}

// ---------------- fused flash attention (unchanged) ----------
__global__ void __launch_bounds__(128)
flash_kernel(const __half* __restrict__ qkv, __half* __restrict__ o)
{
    __shared__ __half KP[2][64][72];
    __shared__ __half Vs[2][64][72];

    int bh = blockIdx.y;
    int b = bh >> 4, h = bh & 15;
    int rt = gridDim.x - 1 - blockIdx.x;
    int q0 = rt * 64;

    int tid = threadIdx.x;
    int lane = tid & 31, wid = tid >> 5;
    int g = lane >> 2, c = lane & 3;
    int wbase = wid * 16;
    const int S3E = 3 * EE;

    auto load_tile = [&](int buf, int st) {
        const __half* Kg = qkv + (size_t)(b * TT + st * 64) * S3E + EE + h * HD;
        const __half* Vg = Kg + EE;
        #pragma unroll
        for (int i = 0; i < 4; i++) {
            int idx = i * 128 + tid;
            int r = idx >> 3, ch = idx & 7;
            cp16(&KP[buf][r][ch * 8], Kg + (size_t)r * S3E + ch * 8);
            cp16(&Vs[buf][r][ch * 8], Vg + (size_t)r * S3E + ch * 8);
        }
        cp_commit();
    };

    load_tile(0, 0);

    uint32_t qf[4][4];
    {
        const __half* Qb = qkv + (size_t)(b * TT + q0 + wbase) * S3E + h * HD;
        const float qs = 0.125f * 1.4426950408889634f;
        const __half2 sc = __floats2half2_rn(qs, qs);
        #pragma unroll
        for (int ks = 0; ks < 4; ks++) {
            int kb = ks * 16;
            __half2 t0 = __hmul2(*(const __half2*)(Qb + (size_t)g       * S3E + kb + 2 * c),     sc);
            __half2 t1 = __hmul2(*(const __half2*)(Qb + (size_t)(g + 8) * S3E + kb + 2 * c),     sc);
            __half2 t2 = __hmul2(*(const __half2*)(Qb + (size_t)g       * S3E + kb + 2 * c + 8), sc);
            __half2 t3 = __hmul2(*(const __half2*)(Qb + (size_t)(g + 8) * S3E + kb + 2 * c + 8), sc);
            qf[ks][0] = *reinterpret_cast<uint32_t*>(&t0);
            qf[ks][1] = *reinterpret_cast<uint32_t*>(&t1);
            qf[ks][2] = *reinterpret_cast<uint32_t*>(&t2);
            qf[ks][3] = *reinterpret_cast<uint32_t*>(&t3);
        }
    }

    float m0 = -INFINITY, m1 = -INFINITY, l0 = 0.f, l1 = 0.f;
    float oacc[8][4];
    #pragma unroll
    for (int nt = 0; nt < 8; nt++)
        #pragma unroll
        for (int k = 0; k < 4; k++) oacc[nt][k] = 0.f;

    for (int st = 0; st <= rt; st++) {
        int cur = st & 1;

        __syncthreads();
        if (st + 1 <= rt) { load_tile(cur ^ 1, st + 1); cp_wait<1>(); }
        else              { cp_wait<0>(); }
        __syncthreads();

        float sacc[8][4];
        #pragma unroll
        for (int nt = 0; nt < 8; nt++)
            #pragma unroll
            for (int k = 0; k < 4; k++) sacc[nt][k] = 0.f;

        #pragma unroll
        for (int ks = 0; ks < 4; ks++) {
            int kb = ks * 16;
            #pragma unroll
            for (int np = 0; np < 4; np++) {
                uint32_t q[4];
                ldsm_x4(q, &KP[cur][np * 16 + (lane & 7) + ((lane & 16) >> 1)][kb + (lane & 8)]);
                uint32_t b0[2] = {q[0], q[1]}, b1[2] = {q[2], q[3]};
                mma_f16(sacc[2 * np],     qf[ks], b0);
                mma_f16(sacc[2 * np + 1], qf[ks], b1);
            }
        }

        if (st == rt) {
            int ql0 = wbase + g, ql1 = ql0 + 8;
            #pragma unroll
            for (int nt = 0; nt < 8; nt++) {
                int kl = nt * 8 + 2 * c;
                if (kl     > ql0) sacc[nt][0] = -1e30f;
                if (kl + 1 > ql0) sacc[nt][1] = -1e30f;
                if (kl     > ql1) sacc[nt][2] = -1e30f;
                if (kl + 1 > ql1) sacc[nt][3] = -1e30f;
            }
        }

        float mx0 = -1e30f, mx1 = -1e30f;
        #pragma unroll
        for (int nt = 0; nt < 8; nt++) {
            mx0 = fmaxf(mx0, fmaxf(sacc[nt][0], sacc[nt][1]));
            mx1 = fmaxf(mx1, fmaxf(sacc[nt][2], sacc[nt][3]));
        }
        mx0 = fmaxf(mx0, __shfl_xor_sync(0xffffffffu, mx0, 1));
        mx0 = fmaxf(mx0, __shfl_xor_sync(0xffffffffu, mx0, 2));
        mx1 = fmaxf(mx1, __shfl_xor_sync(0xffffffffu, mx1, 1));
        mx1 = fmaxf(mx1, __shfl_xor_sync(0xffffffffu, mx1, 2));

        float mn0 = fmaxf(m0, mx0), mn1 = fmaxf(m1, mx1);
        float al0 = ex2(m0 - mn0), al1 = ex2(m1 - mn1);
        m0 = mn0; m1 = mn1;

        float rs0 = 0.f, rs1 = 0.f;
        #pragma unroll
        for (int nt = 0; nt < 8; nt++) {
            float p0 = ex2(sacc[nt][0] - m0);
            float p1 = ex2(sacc[nt][1] - m0);
            float p2 = ex2(sacc[nt][2] - m1);
            float p3 = ex2(sacc[nt][3] - m1);
            sacc[nt][0] = p0; sacc[nt][1] = p1; sacc[nt][2] = p2; sacc[nt][3] = p3;
            rs0 += p0 + p1; rs1 += p2 + p3;
        }
        rs0 += __shfl_xor_sync(0xffffffffu, rs0, 1);
        rs0 += __shfl_xor_sync(0xffffffffu, rs0, 2);
        rs1 += __shfl_xor_sync(0xffffffffu, rs1, 1);
        rs1 += __shfl_xor_sync(0xffffffffu, rs1, 2);
        l0 = l0 * al0 + rs0;
        l1 = l1 * al1 + rs1;

        #pragma unroll
        for (int nt = 0; nt < 8; nt++) {
            oacc[nt][0] *= al0; oacc[nt][1] *= al0;
            oacc[nt][2] *= al1; oacc[nt][3] *= al1;
        }

        __syncthreads();
        #pragma unroll
        for (int nt = 0; nt < 8; nt++) {
            int col = nt * 8 + 2 * c;
            *reinterpret_cast<__half2*>(&KP[cur][wbase + g    ][col]) = __floats2half2_rn(sacc[nt][0], sacc[nt][1]);
            *reinterpret_cast<__half2*>(&KP[cur][wbase + g + 8][col]) = __floats2half2_rn(sacc[nt][2], sacc[nt][3]);
        }
        __syncwarp();

        #pragma unroll
        for (int ks = 0; ks < 4; ks++) {
            int kb = ks * 16;
            uint32_t af[4];
            ldsm_x4(af, &KP[cur][wbase + (lane & 15)][kb + ((lane >> 4) << 3)]);
            #pragma unroll
            for (int np = 0; np < 4; np++) {
                uint32_t q[4];
                ldsm_x4t(q, &Vs[cur][kb + (lane & 15)][np * 16 + ((lane >> 4) << 3)]);
                uint32_t b0[2] = {q[0], q[1]}, b1[2] = {q[2], q[3]};
                mma_f16(oacc[2 * np],     af, b0);
                mma_f16(oacc[2 * np + 1], af, b1);
            }
        }
    }

    float i0 = 1.0f / l0, i1 = 1.0f / l1;
    __half* Ob = o + (size_t)(b * TT + q0 + wbase) * EE + h * HD;
    #pragma unroll
    for (int nt = 0; nt < 8; nt++) {
        int col = nt * 8 + 2 * c;
        *reinterpret_cast<__half2*>(&Ob[(size_t)g * EE + col]) =
            __floats2half2_rn(oacc[nt][0] * i0, oacc[nt][1] * i0);
        *reinterpret_cast<__half2*>(&Ob[(size_t)(g + 8) * EE + col]) =
            __floats2half2_rn(oacc[nt][2] * i1, oacc[nt][3] * i1);
    }
}

// ---------------- launcher ----------------
extern "C" void kernel_launch(void* const* d_in, const int* in_sizes, int n_in,
                              void* d_out, int out_size)
{
    const float* x      = (const float*)d_in[0];
    const float* wq     = (const float*)d_in[1];
    const float* wk     = (const float*)d_in[2];
    const float* wv     = (const float*)d_in[3];
    const float* w_proj = (const float*)d_in[4];
    const float* b_proj = (const float*)d_in[5];
    const float* gamma1 = (const float*)d_in[6];
    const float* beta1  = (const float*)d_in[7];
    const float* gamma2 = (const float*)d_in[8];
    const float* beta2  = (const float*)d_in[9];
    const float* w1     = (const float*)d_in[10];
    const float* b1     = (const float*)d_in[11];
    const float* w2     = (const float*)d_in[12];
    const float* b2     = (const float*)d_in[13];
    float* out = (float*)d_out;

    float *p_x2;
    __half *p_hh, *p_wqkv, *p_qkv, *p_o, *p_h2h, *p_ffn, *p_wp, *p_w1, *p_w2;
    cudaGetSymbolAddress((void**)&p_hh,   g_hh);
    cudaGetSymbolAddress((void**)&p_wqkv, g_wqkv);
    cudaGetSymbolAddress((void**)&p_qkv,  g_qkv);
    cudaGetSymbolAddress((void**)&p_o,    g_o);
    cudaGetSymbolAddress((void**)&p_x2,   g_x2);
    cudaGetSymbolAddress((void**)&p_h2h,  g_h2h);
    cudaGetSymbolAddress((void**)&p_ffn,  g_ffn);
    cudaGetSymbolAddress((void**)&p_wp,   g_wp);
    cudaGetSymbolAddress((void**)&p_w1,   g_w1);
    cudaGetSymbolAddress((void**)&p_w2,   g_w2);

    cudaFuncSetAttribute(mm_fp16<0, true>,  cudaFuncAttributeMaxDynamicSharedMemorySize, MM_SMEM3);
    cudaFuncSetAttribute(mm_fp16<2, true>,  cudaFuncAttributeMaxDynamicSharedMemorySize, MM_SMEM3);
    cudaFuncSetAttribute(mm_fp16<3, false>, cudaFuncAttributeMaxDynamicSharedMemorySize, MM_SMEM3);

    const int CVT_TOTAL4 = (EE * EE + EE * DFF + DFF * EE) / 4;

    // 1) LN1 (fp16 out, single pass)
    ln_kernel<<<NTOK, 256>>>(x, gamma1, beta1, p_hh);
    // 2) pack qkv weights + convert all other weights
    pack_w_kernel<<<(3 * EE * EE) / 256, 256>>>(wq, wk, wv, p_wqkv);
    cvtw_all_kernel<<<(CVT_TOTAL4 + 255) / 256, 256>>>(
        (const float4*)w_proj, (const float4*)w1, (const float4*)w2,
        (__half2*)p_wp, (__half2*)p_w1, (__half2*)p_w2);
    // 3) QKV = h @ Wqkv (fp16 out)
    mm_fp16<0, true><<<dim3(3 * EE / 128, NTOK / 128), 128, MM_SMEM3>>>(p_hh, p_wqkv, nullptr, nullptr, p_qkv, NTOK, 3 * EE, EE);
    // 4-6) fused flash attention (fp16)
    flash_kernel<<<dim3(TT / 64, BHN), 128>>>(p_qkv, p_o);
    // 7) x2 = h + O @ w_proj + b_proj (fp32 out, fp16 residual)
    mm_fp16<3, false><<<dim3(EE / 128, NTOK / 128), 128, MM_SMEM3>>>(p_o, p_wp, b_proj, p_hh, p_x2, NTOK, EE, EE);
    // 8) LN2 (fp16 out, single pass)
    ln_kernel<<<NTOK, 256>>>(p_x2, gamma2, beta2, p_h2h);
    // 9) ffn = relu(h2 @ w1 + b1) (fp16 out)
    mm_fp16<2, true><<<dim3(DFF / 128, NTOK / 128), 128, MM_SMEM3>>>(p_h2h, p_w1, b1, nullptr, p_ffn, NTOK, DFF, EE);
    // 10) out = h2 + ffn @ w2 + b2 (fp32 out, fp16 residual)
    mm_fp16<3, false><<<dim3(EE / 128, NTOK / 128), 128, MM_SMEM3>>>(p_ffn, p_w2, b2, p_h2h, out, NTOK, EE, DFF);
}

// round 16
// speedup vs baseline: 1.3588x; 1.0727x over previous
#include <cuda_runtime.h>
#include <cuda_fp16.h>
#include <math.h>
#include <stdint.h>

// Problem constants
#define BB 2
#define TT 2048
#define EE 1024
#define HH 16
#define HD 64
#define DFF 4096
#define NTOK (BB*TT)          // 4096
#define BHN (BB*HH)           // 32

// ---------------- scratch (device globals) ----------------
__device__ __half g_hh  [NTOK*EE];     // LN1 fp16 (GEMM A + residual)
__device__ __half g_wqkv[EE*3*EE];     // packed fp16 [E,3E]
__device__ __half g_qkv [NTOK*3*EE];   // fp16
__device__ __half g_o   [NTOK*EE];     // fp16
__device__ float  g_x2  [NTOK*EE];     // fp32 (LN2 input)
__device__ __half g_h2h [NTOK*EE];     // LN2 fp16 (GEMM A + residual)
__device__ __half g_ffn [NTOK*DFF];    // fp16
__device__ __half g_wp  [EE*EE];
__device__ __half g_w1  [EE*DFF];
__device__ __half g_w2  [DFF*EE];

// ---------------- helpers ----------------
__device__ __forceinline__ void cp16(void* s, const void* g) {
    uint32_t sa = (uint32_t)__cvta_generic_to_shared(s);
    asm volatile("cp.async.cg.shared.global [%0], [%1], 16;" :: "r"(sa), "l"(g));
}
__device__ __forceinline__ void cp_commit() { asm volatile("cp.async.commit_group;"); }
template<int N> __device__ __forceinline__ void cp_wait() {
    asm volatile("cp.async.wait_group %0;" :: "n"(N));
}
__device__ __forceinline__ void ldsm_x4(uint32_t r[4], const void* p) {
    uint32_t a = (uint32_t)__cvta_generic_to_shared(p);
    asm volatile("ldmatrix.sync.aligned.m8n8.x4.shared.b16 {%0,%1,%2,%3}, [%4];"
        : "=r"(r[0]), "=r"(r[1]), "=r"(r[2]), "=r"(r[3]) : "r"(a));
}
__device__ __forceinline__ void ldsm_x4t(uint32_t r[4], const void* p) {
    uint32_t a = (uint32_t)__cvta_generic_to_shared(p);
    asm volatile("ldmatrix.sync.aligned.m8n8.x4.trans.shared.b16 {%0,%1,%2,%3}, [%4];"
        : "=r"(r[0]), "=r"(r[1]), "=r"(r[2]), "=r"(r[3]) : "r"(a));
}
__device__ __forceinline__ void mma_f16(float acc[4], const uint32_t a[4], const uint32_t b[2]) {
    asm volatile(
        "mma.sync.aligned.m16n8k16.row.col.f32.f16.f16.f32 "
        "{%0,%1,%2,%3},{%4,%5,%6,%7},{%8,%9},{%0,%1,%2,%3};"
        : "+f"(acc[0]), "+f"(acc[1]), "+f"(acc[2]), "+f"(acc[3])
        : "r"(a[0]), "r"(a[1]), "r"(a[2]), "r"(a[3]), "r"(b[0]), "r"(b[1]));
}
__device__ __forceinline__ float ex2(float x) {
    float r;
    asm("ex2.approx.ftz.f32 %0, %1;" : "=f"(r) : "f"(x));
    return r;
}

// ---------------- LayerNorm: single pass, shuffle reductions ----------------
__global__ void ln_kernel(const float* __restrict__ x,
                          const float* __restrict__ gamma,
                          const float* __restrict__ beta,
                          __half* __restrict__ yh)
{
    int row = blockIdx.x;
    int tid = threadIdx.x;
    int lane = tid & 31, wid = tid >> 5;
    const float4* xr = reinterpret_cast<const float4*>(x + (size_t)row * EE);
    __half2* yr = reinterpret_cast<__half2*>(yh + (size_t)row * EE);
    __shared__ float ws[8], wq[8];

    float4 v = xr[tid];
    float s  = v.x + v.y + v.z + v.w;
    float q  = v.x * v.x + v.y * v.y + v.z * v.z + v.w * v.w;
    #pragma unroll
    for (int o = 16; o > 0; o >>= 1) {
        s += __shfl_xor_sync(0xffffffffu, s, o);
        q += __shfl_xor_sync(0xffffffffu, q, o);
    }
    if (lane == 0) { ws[wid] = s; wq[wid] = q; }
    __syncthreads();
    float ts = ws[lane & 7], tq = wq[lane & 7];
    #pragma unroll
    for (int o = 4; o > 0; o >>= 1) {
        ts += __shfl_xor_sync(0xffffffffu, ts, o);
        tq += __shfl_xor_sync(0xffffffffu, tq, o);
    }
    float mean = ts * (1.0f / EE);
    float var  = tq * (1.0f / EE) - mean * mean;
    float inv  = rsqrtf(var + 1e-5f);

    float4 gm = reinterpret_cast<const float4*>(gamma)[tid];
    float4 bt = reinterpret_cast<const float4*>(beta)[tid];
    float o0 = (v.x - mean) * inv * gm.x + bt.x;
    float o1 = (v.y - mean) * inv * gm.y + bt.y;
    float o2 = (v.z - mean) * inv * gm.z + bt.z;
    float o3 = (v.w - mean) * inv * gm.w + bt.w;
    yr[2 * tid]     = __floats2half2_rn(o0, o1);
    yr[2 * tid + 1] = __floats2half2_rn(o2, o3);
}

// ---------------- convert all 3 weight matrices fp32 -> fp16 ----------------
__global__ void cvtw_all_kernel(const float4* __restrict__ wp,
                                const float4* __restrict__ w1,
                                const float4* __restrict__ w2,
                                __half2* __restrict__ op,
                                __half2* __restrict__ o1,
                                __half2* __restrict__ o2)
{
    const int n_p = EE * EE / 4;
    const int n_1 = EE * DFF / 4;
    const int n_2 = DFF * EE / 4;
    int i = blockIdx.x * blockDim.x + threadIdx.x;
    const float4* in; __half2* out; int j;
    if (i < n_p)            { in = wp; out = op; j = i; }
    else if (i < n_p + n_1) { in = w1; out = o1; j = i - n_p; }
    else if (i < n_p + n_1 + n_2) { in = w2; out = o2; j = i - n_p - n_1; }
    else return;
    float4 v = in[j];
    out[2 * j]     = __floats2half2_rn(v.x, v.y);
    out[2 * j + 1] = __floats2half2_rn(v.z, v.w);
}

// ---------------- pack wq/wk/wv [H,E,hd] -> fp16 [E, 3E] ----------------
__global__ void pack_w_kernel(const float* __restrict__ wq,
                              const float* __restrict__ wk,
                              const float* __restrict__ wv,
                              __half* __restrict__ out)
{
    int idx = blockIdx.x * blockDim.x + threadIdx.x;
    const int total = 3 * EE * EE;
    if (idx >= total) return;
    int part = idx / (EE * EE);
    int rem  = idx % (EE * EE);
    int e = rem / EE;
    int c = rem % EE;
    const float* w = (part == 0) ? wq : (part == 1) ? wk : wv;
    out[(size_t)e * (3 * EE) + part * EE + c] =
        __float2half(w[(size_t)(c >> 6) * (EE * HD) + (size_t)e * HD + (c & 63)]);
}

// ---------------- fp16 GEMM: 128x128x32, 4 warps, warp tile 64x64 -----------
// 4-stage ring, 1 sync/iter, cp_wait<2>.
#define MM_SMEM4 ((4*128*40 + 4*32*136) * 2)   // 75776 B dynamic

template <int EPI, bool HOUT>
__global__ void __launch_bounds__(128, 2)
mm_fp16(const __half* __restrict__ A,
        const __half* __restrict__ B,
        const float* __restrict__ bias,
        const __half* __restrict__ res,
        void* __restrict__ Cout,
        int M, int N, int K)
{
    extern __shared__ __half smh[];
    __half (*As)[128][40] = reinterpret_cast<__half(*)[128][40]>(smh);
    __half (*Bs)[32][136] = reinterpret_cast<__half(*)[32][136]>(smh + 4 * 128 * 40);

    int tid = threadIdx.x;
    int lane = tid & 31, wid = tid >> 5;   // 4 warps
    int wm = wid >> 1, wn = wid & 1;       // 2 x 2 warp grid, warp tile 64x64
    int g = lane >> 2, c = lane & 3;
    int rowBase = blockIdx.y * 128;
    int colBase = blockIdx.x * 128;

    float acc[4][8][4];
    #pragma unroll
    for (int i = 0; i < 4; i++)
        #pragma unroll
        for (int j = 0; j < 8; j++)
            #pragma unroll
            for (int k = 0; k < 4; k++) acc[i][j][k] = 0.f;

    auto load_stage = [&](int buf, int kk) {
        #pragma unroll
        for (int i = 0; i < 4; i++) {
            int idx = i * 128 + tid;
            int m = idx >> 2, ch = idx & 3;
            cp16(&As[buf][m][ch * 8], A + (size_t)(rowBase + m) * K + kk + ch * 8);
        }
        #pragma unroll
        for (int i = 0; i < 4; i++) {
            int idx = i * 128 + tid;
            int r = idx >> 4, ch = idx & 15;
            cp16(&Bs[buf][r][ch * 8], B + (size_t)(kk + r) * N + colBase + ch * 8);
        }
        cp_commit();
    };

    int nk = K / 32;
    load_stage(0, 0);
    load_stage(1, 32);
    load_stage(2, 64);

    for (int k0 = 0; k0 < nk; k0++) {
        cp_wait<2>();            // stage k0 resident (3 groups outstanding)
        __syncthreads();         // buffer (k0+3)%4 == (k0-1)%4 fully consumed
        if (k0 + 3 < nk) load_stage((k0 + 3) & 3, (k0 + 3) * 32);
        else             cp_commit();

        int cur = k0 & 3;
        #pragma unroll
        for (int ks = 0; ks < 2; ks++) {
            int kb = ks * 16;
            uint32_t af[4][4];
            #pragma unroll
            for (int mt = 0; mt < 4; mt++) {
                int m0 = wm * 64 + mt * 16;
                ldsm_x4(af[mt], &As[cur][m0 + (lane & 15)][kb + ((lane >> 4) << 3)]);
            }
            uint32_t bf[8][2];
            #pragma unroll
            for (int np = 0; np < 4; np++) {
                int n0 = wn * 64 + np * 16;
                uint32_t q[4];
                ldsm_x4t(q, &Bs[cur][kb + (lane & 15)][n0 + ((lane >> 4) << 3)]);
                bf[2*np][0]   = q[0]; bf[2*np][1]   = q[1];
                bf[2*np+1][0] = q[2]; bf[2*np+1][1] = q[3];
            }
            #pragma unroll
            for (int mt = 0; mt < 4; mt++)
                #pragma unroll
                for (int nt = 0; nt < 8; nt++)
                    mma_f16(acc[mt][nt], af[mt], bf[nt]);
        }
    }

    #pragma unroll
    for (int mt = 0; mt < 4; mt++) {
        int row0 = rowBase + wm * 64 + mt * 16 + g;
        #pragma unroll
        for (int nt = 0; nt < 8; nt++) {
            int col = colBase + wn * 64 + nt * 8 + c * 2;
            float v0 = acc[mt][nt][0], v1 = acc[mt][nt][1];
            float v2 = acc[mt][nt][2], v3 = acc[mt][nt][3];
            if (EPI >= 1) {
                float b0 = bias[col], b1 = bias[col + 1];
                v0 += b0; v1 += b1; v2 += b0; v3 += b1;
            }
            if (EPI == 2) {
                v0 = fmaxf(v0, 0.f); v1 = fmaxf(v1, 0.f);
                v2 = fmaxf(v2, 0.f); v3 = fmaxf(v3, 0.f);
            }
            if (EPI == 3) {
                float2 r0 = __half22float2(*reinterpret_cast<const __half2*>(&res[(size_t)row0 * N + col]));
                float2 r1 = __half22float2(*reinterpret_cast<const __half2*>(&res[(size_t)(row0 + 8) * N + col]));
                v0 += r0.x; v1 += r0.y; v2 += r1.x; v3 += r1.y;
            }
            if (HOUT) {
                __half* Ch = (__half*)Cout;
                *reinterpret_cast<__half2*>(&Ch[(size_t)row0 * N + col])       = __floats2half2_rn(v0, v1);
                *reinterpret_cast<__half2*>(&Ch[(size_t)(row0 + 8) * N + col]) = __floats2half2_rn(v2, v3);
            } else {
                float* Cf = (float*)Cout;
                *reinterpret_cast<float2*>(&Cf[(size_t)row0 * N + col])       = make_float2(v0, v1);
                *reinterpret_cast<float2*>(&Cf[(size_t)(row0 + 8) * N + col]) = make_float2(v2, v3);
            }
        }
    }
}

// ---------------- fused flash attention (unchanged) ----------
__global__ void __launch_bounds__(128)
flash_kernel(const __half* __restrict__ qkv, __half* __restrict__ o)
{
    __shared__ __half KP[2][64][72];
    __shared__ __half Vs[2][64][72];

    int bh = blockIdx.y;
    int b = bh >> 4, h = bh & 15;
    int rt = gridDim.x - 1 - blockIdx.x;
    int q0 = rt * 64;

    int tid = threadIdx.x;
    int lane = tid & 31, wid = tid >> 5;
    int g = lane >> 2, c = lane & 3;
    int wbase = wid * 16;
    const int S3E = 3 * EE;

    auto load_tile = [&](int buf, int st) {
        const __half* Kg = qkv + (size_t)(b * TT + st * 64) * S3E + EE + h * HD;
        const __half* Vg = Kg + EE;
        #pragma unroll
        for (int i = 0; i < 4; i++) {
            int idx = i * 128 + tid;
            int r = idx >> 3, ch = idx & 7;
            cp16(&KP[buf][r][ch * 8], Kg + (size_t)r * S3E + ch * 8);
            cp16(&Vs[buf][r][ch * 8], Vg + (size_t)r * S3E + ch * 8);
        }
        cp_commit();
    };

    load_tile(0, 0);

    uint32_t qf[4][4];
    {
        const __half* Qb = qkv + (size_t)(b * TT + q0 + wbase) * S3E + h * HD;
        const float qs = 0.125f * 1.4426950408889634f;
        const __half2 sc = __floats2half2_rn(qs, qs);
        #pragma unroll
        for (int ks = 0; ks < 4; ks++) {
            int kb = ks * 16;
            __half2 t0 = __hmul2(*(const __half2*)(Qb + (size_t)g       * S3E + kb + 2 * c),     sc);
            __half2 t1 = __hmul2(*(const __half2*)(Qb + (size_t)(g + 8) * S3E + kb + 2 * c),     sc);
            __half2 t2 = __hmul2(*(const __half2*)(Qb + (size_t)g       * S3E + kb + 2 * c + 8), sc);
            __half2 t3 = __hmul2(*(const __half2*)(Qb + (size_t)(g + 8) * S3E + kb + 2 * c + 8), sc);
            qf[ks][0] = *reinterpret_cast<uint32_t*>(&t0);
            qf[ks][1] = *reinterpret_cast<uint32_t*>(&t1);
            qf[ks][2] = *reinterpret_cast<uint32_t*>(&t2);
            qf[ks][3] = *reinterpret_cast<uint32_t*>(&t3);
        }
    }

    float m0 = -INFINITY, m1 = -INFINITY, l0 = 0.f, l1 = 0.f;
    float oacc[8][4];
    #pragma unroll
    for (int nt = 0; nt < 8; nt++)
        #pragma unroll
        for (int k = 0; k < 4; k++) oacc[nt][k] = 0.f;

    for (int st = 0; st <= rt; st++) {
        int cur = st & 1;

        __syncthreads();
        if (st + 1 <= rt) { load_tile(cur ^ 1, st + 1); cp_wait<1>(); }
        else              { cp_wait<0>(); }
        __syncthreads();

        float sacc[8][4];
        #pragma unroll
        for (int nt = 0; nt < 8; nt++)
            #pragma unroll
            for (int k = 0; k < 4; k++) sacc[nt][k] = 0.f;

        #pragma unroll
        for (int ks = 0; ks < 4; ks++) {
            int kb = ks * 16;
            #pragma unroll
            for (int np = 0; np < 4; np++) {
                uint32_t q[4];
                ldsm_x4(q, &KP[cur][np * 16 + (lane & 7) + ((lane & 16) >> 1)][kb + (lane & 8)]);
                uint32_t b0[2] = {q[0], q[1]}, b1[2] = {q[2], q[3]};
                mma_f16(sacc[2 * np],     qf[ks], b0);
                mma_f16(sacc[2 * np + 1], qf[ks], b1);
            }
        }

        if (st == rt) {
            int ql0 = wbase + g, ql1 = ql0 + 8;
            #pragma unroll
            for (int nt = 0; nt < 8; nt++) {
                int kl = nt * 8 + 2 * c;
                if (kl     > ql0) sacc[nt][0] = -1e30f;
                if (kl + 1 > ql0) sacc[nt][1] = -1e30f;
                if (kl     > ql1) sacc[nt][2] = -1e30f;
                if (kl + 1 > ql1) sacc[nt][3] = -1e30f;
            }
        }

        float mx0 = -1e30f, mx1 = -1e30f;
        #pragma unroll
        for (int nt = 0; nt < 8; nt++) {
            mx0 = fmaxf(mx0, fmaxf(sacc[nt][0], sacc[nt][1]));
            mx1 = fmaxf(mx1, fmaxf(sacc[nt][2], sacc[nt][3]));
        }
        mx0 = fmaxf(mx0, __shfl_xor_sync(0xffffffffu, mx0, 1));
        mx0 = fmaxf(mx0, __shfl_xor_sync(0xffffffffu, mx0, 2));
        mx1 = fmaxf(mx1, __shfl_xor_sync(0xffffffffu, mx1, 1));
        mx1 = fmaxf(mx1, __shfl_xor_sync(0xffffffffu, mx1, 2));

        float mn0 = fmaxf(m0, mx0), mn1 = fmaxf(m1, mx1);
        float al0 = ex2(m0 - mn0), al1 = ex2(m1 - mn1);
        m0 = mn0; m1 = mn1;

        float rs0 = 0.f, rs1 = 0.f;
        #pragma unroll
        for (int nt = 0; nt < 8; nt++) {
            float p0 = ex2(sacc[nt][0] - m0);
            float p1 = ex2(sacc[nt][1] - m0);
            float p2 = ex2(sacc[nt][2] - m1);
            float p3 = ex2(sacc[nt][3] - m1);
            sacc[nt][0] = p0; sacc[nt][1] = p1; sacc[nt][2] = p2; sacc[nt][3] = p3;
            rs0 += p0 + p1; rs1 += p2 + p3;
        }
        rs0 += __shfl_xor_sync(0xffffffffu, rs0, 1);
        rs0 += __shfl_xor_sync(0xffffffffu, rs0, 2);
        rs1 += __shfl_xor_sync(0xffffffffu, rs1, 1);
        rs1 += __shfl_xor_sync(0xffffffffu, rs1, 2);
        l0 = l0 * al0 + rs0;
        l1 = l1 * al1 + rs1;

        #pragma unroll
        for (int nt = 0; nt < 8; nt++) {
            oacc[nt][0] *= al0; oacc[nt][1] *= al0;
            oacc[nt][2] *= al1; oacc[nt][3] *= al1;
        }

        __syncthreads();
        #pragma unroll
        for (int nt = 0; nt < 8; nt++) {
            int col = nt * 8 + 2 * c;
            *reinterpret_cast<__half2*>(&KP[cur][wbase + g    ][col]) = __floats2half2_rn(sacc[nt][0], sacc[nt][1]);
            *reinterpret_cast<__half2*>(&KP[cur][wbase + g + 8][col]) = __floats2half2_rn(sacc[nt][2], sacc[nt][3]);
        }
        __syncwarp();

        #pragma unroll
        for (int ks = 0; ks < 4; ks++) {
            int kb = ks * 16;
            uint32_t af[4];
            ldsm_x4(af, &KP[cur][wbase + (lane & 15)][kb + ((lane >> 4) << 3)]);
            #pragma unroll
            for (int np = 0; np < 4; np++) {
                uint32_t q[4];
                ldsm_x4t(q, &Vs[cur][kb + (lane & 15)][np * 16 + ((lane >> 4) << 3)]);
                uint32_t b0[2] = {q[0], q[1]}, b1[2] = {q[2], q[3]};
                mma_f16(oacc[2 * np],     af, b0);
                mma_f16(oacc[2 * np + 1], af, b1);
            }
        }
    }

    float i0 = 1.0f / l0, i1 = 1.0f / l1;
    __half* Ob = o + (size_t)(b * TT + q0 + wbase) * EE + h * HD;
    #pragma unroll
    for (int nt = 0; nt < 8; nt++) {
        int col = nt * 8 + 2 * c;
        *reinterpret_cast<__half2*>(&Ob[(size_t)g * EE + col]) =
            __floats2half2_rn(oacc[nt][0] * i0, oacc[nt][1] * i0);
        *reinterpret_cast<__half2*>(&Ob[(size_t)(g + 8) * EE + col]) =
            __floats2half2_rn(oacc[nt][2] * i1, oacc[nt][3] * i1);
    }
}

// ---------------- launcher ----------------
extern "C" void kernel_launch(void* const* d_in, const int* in_sizes, int n_in,
                              void* d_out, int out_size)
{
    const float* x      = (const float*)d_in[0];
    const float* wq     = (const float*)d_in[1];
    const float* wk     = (const float*)d_in[2];
    const float* wv     = (const float*)d_in[3];
    const float* w_proj = (const float*)d_in[4];
    const float* b_proj = (const float*)d_in[5];
    const float* gamma1 = (const float*)d_in[6];
    const float* beta1  = (const float*)d_in[7];
    const float* gamma2 = (const float*)d_in[8];
    const float* beta2  = (const float*)d_in[9];
    const float* w1     = (const float*)d_in[10];
    const float* b1     = (const float*)d_in[11];
    const float* w2     = (const float*)d_in[12];
    const float* b2     = (const float*)d_in[13];
    float* out = (float*)d_out;

    float *p_x2;
    __half *p_hh, *p_wqkv, *p_qkv, *p_o, *p_h2h, *p_ffn, *p_wp, *p_w1, *p_w2;
    cudaGetSymbolAddress((void**)&p_hh,   g_hh);
    cudaGetSymbolAddress((void**)&p_wqkv, g_wqkv);
    cudaGetSymbolAddress((void**)&p_qkv,  g_qkv);
    cudaGetSymbolAddress((void**)&p_o,    g_o);
    cudaGetSymbolAddress((void**)&p_x2,   g_x2);
    cudaGetSymbolAddress((void**)&p_h2h,  g_h2h);
    cudaGetSymbolAddress((void**)&p_ffn,  g_ffn);
    cudaGetSymbolAddress((void**)&p_wp,   g_wp);
    cudaGetSymbolAddress((void**)&p_w1,   g_w1);
    cudaGetSymbolAddress((void**)&p_w2,   g_w2);

    cudaFuncSetAttribute(mm_fp16<0, true>,  cudaFuncAttributeMaxDynamicSharedMemorySize, MM_SMEM4);
    cudaFuncSetAttribute(mm_fp16<2, true>,  cudaFuncAttributeMaxDynamicSharedMemorySize, MM_SMEM4);
    cudaFuncSetAttribute(mm_fp16<3, false>, cudaFuncAttributeMaxDynamicSharedMemorySize, MM_SMEM4);

    const int CVT_TOTAL4 = (EE * EE + EE * DFF + DFF * EE) / 4;

    // 1) LN1 (fp16 out, single pass)
    ln_kernel<<<NTOK, 256>>>(x, gamma1, beta1, p_hh);
    // 2) pack qkv weights + convert all other weights
    pack_w_kernel<<<(3 * EE * EE) / 256, 256>>>(wq, wk, wv, p_wqkv);
    cvtw_all_kernel<<<(CVT_TOTAL4 + 255) / 256, 256>>>(
        (const float4*)w_proj, (const float4*)w1, (const float4*)w2,
        (__half2*)p_wp, (__half2*)p_w1, (__half2*)p_w2);
    // 3) QKV = h @ Wqkv (fp16 out)
    mm_fp16<0, true><<<dim3(3 * EE / 128, NTOK / 128), 128, MM_SMEM4>>>(p_hh, p_wqkv, nullptr, nullptr, p_qkv, NTOK, 3 * EE, EE);
    // 4-6) fused flash attention (fp16)
    flash_kernel<<<dim3(TT / 64, BHN), 128>>>(p_qkv, p_o);
    // 7) x2 = h + O @ w_proj + b_proj (fp32 out, fp16 residual)
    mm_fp16<3, false><<<dim3(EE / 128, NTOK / 128), 128, MM_SMEM4>>>(p_o, p_wp, b_proj, p_hh, p_x2, NTOK, EE, EE);
    // 8) LN2 (fp16 out, single pass)
    ln_kernel<<<NTOK, 256>>>(p_x2, gamma2, beta2, p_h2h);
    // 9) ffn = relu(h2 @ w1 + b1) (fp16 out)
    mm_fp16<2, true><<<dim3(DFF / 128, NTOK / 128), 128, MM_SMEM4>>>(p_h2h, p_w1, b1, nullptr, p_ffn, NTOK, DFF, EE);
    // 10) out = h2 + ffn @ w2 + b2 (fp32 out, fp16 residual)
    mm_fp16<3, false><<<dim3(EE / 128, NTOK / 128), 128, MM_SMEM4>>>(p_ffn, p_w2, b2, p_h2h, out, NTOK, EE, DFF);
}

// round 17
// speedup vs baseline: 1.3659x; 1.0052x over previous
#include <cuda_runtime.h>
#include <cuda_fp16.h>
#include <math.h>
#include <stdint.h>

// Problem constants
#define BB 2
#define TT 2048
#define EE 1024
#define HH 16
#define HD 64
#define DFF 4096
#define NTOK (BB*TT)          // 4096
#define BHN (BB*HH)           // 32

// ---------------- scratch (device globals) ----------------
__device__ __half g_hh  [NTOK*EE];     // LN1 fp16 (GEMM A + residual)
__device__ __half g_wqkv[EE*3*EE];     // packed fp16 [E,3E]
__device__ __half g_qkv [NTOK*3*EE];   // fp16
__device__ __half g_o   [NTOK*EE];     // fp16
__device__ float  g_x2  [NTOK*EE];     // fp32 (LN2 input)
__device__ __half g_h2h [NTOK*EE];     // LN2 fp16 (GEMM A + residual)
__device__ __half g_ffn [NTOK*DFF];    // fp16
__device__ __half g_wp  [EE*EE];
__device__ __half g_w1  [EE*DFF];
__device__ __half g_w2  [DFF*EE];

// ---------------- helpers ----------------
__device__ __forceinline__ void cp16(void* s, const void* g) {
    uint32_t sa = (uint32_t)__cvta_generic_to_shared(s);
    asm volatile("cp.async.cg.shared.global [%0], [%1], 16;" :: "r"(sa), "l"(g));
}
__device__ __forceinline__ void cp_commit() { asm volatile("cp.async.commit_group;"); }
template<int N> __device__ __forceinline__ void cp_wait() {
    asm volatile("cp.async.wait_group %0;" :: "n"(N));
}
__device__ __forceinline__ void ldsm_x4(uint32_t r[4], const void* p) {
    uint32_t a = (uint32_t)__cvta_generic_to_shared(p);
    asm volatile("ldmatrix.sync.aligned.m8n8.x4.shared.b16 {%0,%1,%2,%3}, [%4];"
        : "=r"(r[0]), "=r"(r[1]), "=r"(r[2]), "=r"(r[3]) : "r"(a));
}
__device__ __forceinline__ void ldsm_x4t(uint32_t r[4], const void* p) {
    uint32_t a = (uint32_t)__cvta_generic_to_shared(p);
    asm volatile("ldmatrix.sync.aligned.m8n8.x4.trans.shared.b16 {%0,%1,%2,%3}, [%4];"
        : "=r"(r[0]), "=r"(r[1]), "=r"(r[2]), "=r"(r[3]) : "r"(a));
}
__device__ __forceinline__ void mma_f16(float acc[4], const uint32_t a[4], const uint32_t b[2]) {
    asm volatile(
        "mma.sync.aligned.m16n8k16.row.col.f32.f16.f16.f32 "
        "{%0,%1,%2,%3},{%4,%5,%6,%7},{%8,%9},{%0,%1,%2,%3};"
        : "+f"(acc[0]), "+f"(acc[1]), "+f"(acc[2]), "+f"(acc[3])
        : "r"(a[0]), "r"(a[1]), "r"(a[2]), "r"(a[3]), "r"(b[0]), "r"(b[1]));
}
__device__ __forceinline__ float ex2(float x) {
    float r;
    asm("ex2.approx.ftz.f32 %0, %1;" : "=f"(r) : "f"(x));
    return r;
}

// ---------------- LayerNorm: single pass, shuffle reductions ----------------
__global__ void ln_kernel(const float* __restrict__ x,
                          const float* __restrict__ gamma,
                          const float* __restrict__ beta,
                          __half* __restrict__ yh)
{
    int row = blockIdx.x;
    int tid = threadIdx.x;
    int lane = tid & 31, wid = tid >> 5;
    const float4* xr = reinterpret_cast<const float4*>(x + (size_t)row * EE);
    __half2* yr = reinterpret_cast<__half2*>(yh + (size_t)row * EE);
    __shared__ float ws[8], wq[8];

    float4 v = xr[tid];
    float s  = v.x + v.y + v.z + v.w;
    float q  = v.x * v.x + v.y * v.y + v.z * v.z + v.w * v.w;
    #pragma unroll
    for (int o = 16; o > 0; o >>= 1) {
        s += __shfl_xor_sync(0xffffffffu, s, o);
        q += __shfl_xor_sync(0xffffffffu, q, o);
    }
    if (lane == 0) { ws[wid] = s; wq[wid] = q; }
    __syncthreads();
    float ts = ws[lane & 7], tq = wq[lane & 7];
    #pragma unroll
    for (int o = 4; o > 0; o >>= 1) {
        ts += __shfl_xor_sync(0xffffffffu, ts, o);
        tq += __shfl_xor_sync(0xffffffffu, tq, o);
    }
    float mean = ts * (1.0f / EE);
    float var  = tq * (1.0f / EE) - mean * mean;
    float inv  = rsqrtf(var + 1e-5f);

    float4 gm = reinterpret_cast<const float4*>(gamma)[tid];
    float4 bt = reinterpret_cast<const float4*>(beta)[tid];
    float o0 = (v.x - mean) * inv * gm.x + bt.x;
    float o1 = (v.y - mean) * inv * gm.y + bt.y;
    float o2 = (v.z - mean) * inv * gm.z + bt.z;
    float o3 = (v.w - mean) * inv * gm.w + bt.w;
    yr[2 * tid]     = __floats2half2_rn(o0, o1);
    yr[2 * tid + 1] = __floats2half2_rn(o2, o3);
}

// ---------------- convert all 3 weight matrices fp32 -> fp16 ----------------
__global__ void cvtw_all_kernel(const float4* __restrict__ wp,
                                const float4* __restrict__ w1,
                                const float4* __restrict__ w2,
                                __half2* __restrict__ op,
                                __half2* __restrict__ o1,
                                __half2* __restrict__ o2)
{
    const int n_p = EE * EE / 4;
    const int n_1 = EE * DFF / 4;
    const int n_2 = DFF * EE / 4;
    int i = blockIdx.x * blockDim.x + threadIdx.x;
    const float4* in; __half2* out; int j;
    if (i < n_p)            { in = wp; out = op; j = i; }
    else if (i < n_p + n_1) { in = w1; out = o1; j = i - n_p; }
    else if (i < n_p + n_1 + n_2) { in = w2; out = o2; j = i - n_p - n_1; }
    else return;
    float4 v = in[j];
    out[2 * j]     = __floats2half2_rn(v.x, v.y);
    out[2 * j + 1] = __floats2half2_rn(v.z, v.w);
}

// ---------------- pack wq/wk/wv [H,E,hd] -> fp16 [E, 3E] ----------------
__global__ void pack_w_kernel(const float* __restrict__ wq,
                              const float* __restrict__ wk,
                              const float* __restrict__ wv,
                              __half* __restrict__ out)
{
    int idx = blockIdx.x * blockDim.x + threadIdx.x;
    const int total = 3 * EE * EE;
    if (idx >= total) return;
    int part = idx / (EE * EE);
    int rem  = idx % (EE * EE);
    int e = rem / EE;
    int c = rem % EE;
    const float* w = (part == 0) ? wq : (part == 1) ? wk : wv;
    out[(size_t)e * (3 * EE) + part * EE + c] =
        __float2half(w[(size_t)(c >> 6) * (EE * HD) + (size_t)e * HD + (c & 63)]);
}

// ---------------- fp16 GEMM: 128x128x32, 4 warps, warp tile 64x64 -----------
// 4-stage ring, 1 sync/iter, cp_wait<2>.  (R15 winner, unchanged)
#define MM_SMEM4 ((4*128*40 + 4*32*136) * 2)   // 75776 B dynamic

template <int EPI, bool HOUT>
__global__ void __launch_bounds__(128, 2)
mm_fp16(const __half* __restrict__ A,
        const __half* __restrict__ B,
        const float* __restrict__ bias,
        const __half* __restrict__ res,
        void* __restrict__ Cout,
        int M, int N, int K)
{
    extern __shared__ __half smh[];
    __half (*As)[128][40] = reinterpret_cast<__half(*)[128][40]>(smh);
    __half (*Bs)[32][136] = reinterpret_cast<__half(*)[32][136]>(smh + 4 * 128 * 40);

    int tid = threadIdx.x;
    int lane = tid & 31, wid = tid >> 5;   // 4 warps
    int wm = wid >> 1, wn = wid & 1;       // 2 x 2 warp grid, warp tile 64x64
    int g = lane >> 2, c = lane & 3;
    int rowBase = blockIdx.y * 128;
    int colBase = blockIdx.x * 128;

    float acc[4][8][4];
    #pragma unroll
    for (int i = 0; i < 4; i++)
        #pragma unroll
        for (int j = 0; j < 8; j++)
            #pragma unroll
            for (int k = 0; k < 4; k++) acc[i][j][k] = 0.f;

    auto load_stage = [&](int buf, int kk) {
        #pragma unroll
        for (int i = 0; i < 4; i++) {
            int idx = i * 128 + tid;
            int m = idx >> 2, ch = idx & 3;
            cp16(&As[buf][m][ch * 8], A + (size_t)(rowBase + m) * K + kk + ch * 8);
        }
        #pragma unroll
        for (int i = 0; i < 4; i++) {
            int idx = i * 128 + tid;
            int r = idx >> 4, ch = idx & 15;
            cp16(&Bs[buf][r][ch * 8], B + (size_t)(kk + r) * N + colBase + ch * 8);
        }
        cp_commit();
    };

    int nk = K / 32;
    load_stage(0, 0);
    load_stage(1, 32);
    load_stage(2, 64);

    for (int k0 = 0; k0 < nk; k0++) {
        cp_wait<2>();
        __syncthreads();
        if (k0 + 3 < nk) load_stage((k0 + 3) & 3, (k0 + 3) * 32);
        else             cp_commit();

        int cur = k0 & 3;
        #pragma unroll
        for (int ks = 0; ks < 2; ks++) {
            int kb = ks * 16;
            uint32_t af[4][4];
            #pragma unroll
            for (int mt = 0; mt < 4; mt++) {
                int m0 = wm * 64 + mt * 16;
                ldsm_x4(af[mt], &As[cur][m0 + (lane & 15)][kb + ((lane >> 4) << 3)]);
            }
            uint32_t bf[8][2];
            #pragma unroll
            for (int np = 0; np < 4; np++) {
                int n0 = wn * 64 + np * 16;
                uint32_t q[4];
                ldsm_x4t(q, &Bs[cur][kb + (lane & 15)][n0 + ((lane >> 4) << 3)]);
                bf[2*np][0]   = q[0]; bf[2*np][1]   = q[1];
                bf[2*np+1][0] = q[2]; bf[2*np+1][1] = q[3];
            }
            #pragma unroll
            for (int mt = 0; mt < 4; mt++)
                #pragma unroll
                for (int nt = 0; nt < 8; nt++)
                    mma_f16(acc[mt][nt], af[mt], bf[nt]);
        }
    }

    #pragma unroll
    for (int mt = 0; mt < 4; mt++) {
        int row0 = rowBase + wm * 64 + mt * 16 + g;
        #pragma unroll
        for (int nt = 0; nt < 8; nt++) {
            int col = colBase + wn * 64 + nt * 8 + c * 2;
            float v0 = acc[mt][nt][0], v1 = acc[mt][nt][1];
            float v2 = acc[mt][nt][2], v3 = acc[mt][nt][3];
            if (EPI >= 1) {
                float b0 = bias[col], b1 = bias[col + 1];
                v0 += b0; v1 += b1; v2 += b0; v3 += b1;
            }
            if (EPI == 2) {
                v0 = fmaxf(v0, 0.f); v1 = fmaxf(v1, 0.f);
                v2 = fmaxf(v2, 0.f); v3 = fmaxf(v3, 0.f);
            }
            if (EPI == 3) {
                float2 r0 = __half22float2(*reinterpret_cast<const __half2*>(&res[(size_t)row0 * N + col]));
                float2 r1 = __half22float2(*reinterpret_cast<const __half2*>(&res[(size_t)(row0 + 8) * N + col]));
                v0 += r0.x; v1 += r0.y; v2 += r1.x; v3 += r1.y;
            }
            if (HOUT) {
                __half* Ch = (__half*)Cout;
                *reinterpret_cast<__half2*>(&Ch[(size_t)row0 * N + col])       = __floats2half2_rn(v0, v1);
                *reinterpret_cast<__half2*>(&Ch[(size_t)(row0 + 8) * N + col]) = __floats2half2_rn(v2, v3);
            } else {
                float* Cf = (float*)Cout;
                *reinterpret_cast<float2*>(&Cf[(size_t)row0 * N + col])       = make_float2(v0, v1);
                *reinterpret_cast<float2*>(&Cf[(size_t)(row0 + 8) * N + col]) = make_float2(v2, v3);
            }
        }
    }
}

// ---------------- fused flash attention: 3-stage KV ring + P buffer ---------
// grid: (T/64, BHN); block: 128 (4 warps, 16 query rows each)
// One __syncthreads per KV tile; P in its own buffer (warp-private rows).
__global__ void __launch_bounds__(128)
flash_kernel(const __half* __restrict__ qkv, __half* __restrict__ o)
{
    __shared__ __half Ks[3][64][72];
    __shared__ __half Vs[3][64][72];
    __shared__ __half Ps[64][72];

    int bh = blockIdx.y;
    int b = bh >> 4, h = bh & 15;
    int rt = gridDim.x - 1 - blockIdx.x;   // heavy CTAs first
    int q0 = rt * 64;

    int tid = threadIdx.x;
    int lane = tid & 31, wid = tid >> 5;
    int g = lane >> 2, c = lane & 3;
    int wbase = wid * 16;
    const int S3E = 3 * EE;

    auto load_tile = [&](int buf, int st) {
        const __half* Kg = qkv + (size_t)(b * TT + st * 64) * S3E + EE + h * HD;
        const __half* Vg = Kg + EE;
        #pragma unroll
        for (int i = 0; i < 4; i++) {
            int idx = i * 128 + tid;
            int r = idx >> 3, ch = idx & 7;
            cp16(&Ks[buf][r][ch * 8], Kg + (size_t)r * S3E + ch * 8);
            cp16(&Vs[buf][r][ch * 8], Vg + (size_t)r * S3E + ch * 8);
        }
        cp_commit();
    };

    // prologue: tiles 0 and 1 in flight (tile index <= 31 always valid memory)
    load_tile(0, 0);
    load_tile(1, rt >= 1 ? 1 : 0);

    uint32_t qf[4][4];
    {
        const __half* Qb = qkv + (size_t)(b * TT + q0 + wbase) * S3E + h * HD;
        const float qs = 0.125f * 1.4426950408889634f;
        const __half2 sc = __floats2half2_rn(qs, qs);
        #pragma unroll
        for (int ks = 0; ks < 4; ks++) {
            int kb = ks * 16;
            __half2 t0 = __hmul2(*(const __half2*)(Qb + (size_t)g       * S3E + kb + 2 * c),     sc);
            __half2 t1 = __hmul2(*(const __half2*)(Qb + (size_t)(g + 8) * S3E + kb + 2 * c),     sc);
            __half2 t2 = __hmul2(*(const __half2*)(Qb + (size_t)g       * S3E + kb + 2 * c + 8), sc);
            __half2 t3 = __hmul2(*(const __half2*)(Qb + (size_t)(g + 8) * S3E + kb + 2 * c + 8), sc);
            qf[ks][0] = *reinterpret_cast<uint32_t*>(&t0);
            qf[ks][1] = *reinterpret_cast<uint32_t*>(&t1);
            qf[ks][2] = *reinterpret_cast<uint32_t*>(&t2);
            qf[ks][3] = *reinterpret_cast<uint32_t*>(&t3);
        }
    }

    float m0 = -INFINITY, m1 = -INFINITY, l0 = 0.f, l1 = 0.f;
    float oacc[8][4];
    #pragma unroll
    for (int nt = 0; nt < 8; nt++)
        #pragma unroll
        for (int k = 0; k < 4; k++) oacc[nt][k] = 0.f;

    for (int st = 0; st <= rt; st++) {
        cp_wait<1>();            // tile st resident
        __syncthreads();         // all warps done with iter st-1 (buffer (st+2)%3 free)
        if (st + 2 <= rt) load_tile((st + 2) % 3, st + 2);
        else              cp_commit();

        int cur = st % 3;

        // S = Q @ K^T
        float sacc[8][4];
        #pragma unroll
        for (int nt = 0; nt < 8; nt++)
            #pragma unroll
            for (int k = 0; k < 4; k++) sacc[nt][k] = 0.f;

        #pragma unroll
        for (int ks = 0; ks < 4; ks++) {
            int kb = ks * 16;
            #pragma unroll
            for (int np = 0; np < 4; np++) {
                uint32_t q[4];
                ldsm_x4(q, &Ks[cur][np * 16 + (lane & 7) + ((lane & 16) >> 1)][kb + (lane & 8)]);
                uint32_t b0[2] = {q[0], q[1]}, b1[2] = {q[2], q[3]};
                mma_f16(sacc[2 * np],     qf[ks], b0);
                mma_f16(sacc[2 * np + 1], qf[ks], b1);
            }
        }

        // causal mask on diagonal tile only
        if (st == rt) {
            int ql0 = wbase + g, ql1 = ql0 + 8;
            #pragma unroll
            for (int nt = 0; nt < 8; nt++) {
                int kl = nt * 8 + 2 * c;
                if (kl     > ql0) sacc[nt][0] = -1e30f;
                if (kl + 1 > ql0) sacc[nt][1] = -1e30f;
                if (kl     > ql1) sacc[nt][2] = -1e30f;
                if (kl + 1 > ql1) sacc[nt][3] = -1e30f;
            }
        }

        // online softmax (exp2 domain)
        float mx0 = -1e30f, mx1 = -1e30f;
        #pragma unroll
        for (int nt = 0; nt < 8; nt++) {
            mx0 = fmaxf(mx0, fmaxf(sacc[nt][0], sacc[nt][1]));
            mx1 = fmaxf(mx1, fmaxf(sacc[nt][2], sacc[nt][3]));
        }
        mx0 = fmaxf(mx0, __shfl_xor_sync(0xffffffffu, mx0, 1));
        mx0 = fmaxf(mx0, __shfl_xor_sync(0xffffffffu, mx0, 2));
        mx1 = fmaxf(mx1, __shfl_xor_sync(0xffffffffu, mx1, 1));
        mx1 = fmaxf(mx1, __shfl_xor_sync(0xffffffffu, mx1, 2));

        float mn0 = fmaxf(m0, mx0), mn1 = fmaxf(m1, mx1);
        float al0 = ex2(m0 - mn0), al1 = ex2(m1 - mn1);
        m0 = mn0; m1 = mn1;

        float rs0 = 0.f, rs1 = 0.f;
        #pragma unroll
        for (int nt = 0; nt < 8; nt++) {
            float p0 = ex2(sacc[nt][0] - m0);
            float p1 = ex2(sacc[nt][1] - m0);
            float p2 = ex2(sacc[nt][2] - m1);
            float p3 = ex2(sacc[nt][3] - m1);
            sacc[nt][0] = p0; sacc[nt][1] = p1; sacc[nt][2] = p2; sacc[nt][3] = p3;
            rs0 += p0 + p1; rs1 += p2 + p3;
        }
        rs0 += __shfl_xor_sync(0xffffffffu, rs0, 1);
        rs0 += __shfl_xor_sync(0xffffffffu, rs0, 2);
        rs1 += __shfl_xor_sync(0xffffffffu, rs1, 1);
        rs1 += __shfl_xor_sync(0xffffffffu, rs1, 2);
        l0 = l0 * al0 + rs0;
        l1 = l1 * al1 + rs1;

        #pragma unroll
        for (int nt = 0; nt < 8; nt++) {
            oacc[nt][0] *= al0; oacc[nt][1] *= al0;
            oacc[nt][2] *= al1; oacc[nt][3] *= al1;
        }

        // store P into its own buffer (warp-private rows — no CTA sync needed)
        #pragma unroll
        for (int nt = 0; nt < 8; nt++) {
            int col = nt * 8 + 2 * c;
            *reinterpret_cast<__half2*>(&Ps[wbase + g    ][col]) = __floats2half2_rn(sacc[nt][0], sacc[nt][1]);
            *reinterpret_cast<__half2*>(&Ps[wbase + g + 8][col]) = __floats2half2_rn(sacc[nt][2], sacc[nt][3]);
        }
        __syncwarp();

        // O += P @ V
        #pragma unroll
        for (int ks = 0; ks < 4; ks++) {
            int kb = ks * 16;
            uint32_t af[4];
            ldsm_x4(af, &Ps[wbase + (lane & 15)][kb + ((lane >> 4) << 3)]);
            #pragma unroll
            for (int np = 0; np < 4; np++) {
                uint32_t q[4];
                ldsm_x4t(q, &Vs[cur][kb + (lane & 15)][np * 16 + ((lane >> 4) << 3)]);
                uint32_t b0[2] = {q[0], q[1]}, b1[2] = {q[2], q[3]};
                mma_f16(oacc[2 * np],     af, b0);
                mma_f16(oacc[2 * np + 1], af, b1);
            }
        }
    }

    float i0 = 1.0f / l0, i1 = 1.0f / l1;
    __half* Ob = o + (size_t)(b * TT + q0 + wbase) * EE + h * HD;
    #pragma unroll
    for (int nt = 0; nt < 8; nt++) {
        int col = nt * 8 + 2 * c;
        *reinterpret_cast<__half2*>(&Ob[(size_t)g * EE + col]) =
            __floats2half2_rn(oacc[nt][0] * i0, oacc[nt][1] * i0);
        *reinterpret_cast<__half2*>(&Ob[(size_t)(g + 8) * EE + col]) =
            __floats2half2_rn(oacc[nt][2] * i1, oacc[nt][3] * i1);
    }
}

// ---------------- launcher ----------------
extern "C" void kernel_launch(void* const* d_in, const int* in_sizes, int n_in,
                              void* d_out, int out_size)
{
    const float* x      = (const float*)d_in[0];
    const float* wq     = (const float*)d_in[1];
    const float* wk     = (const float*)d_in[2];
    const float* wv     = (const float*)d_in[3];
    const float* w_proj = (const float*)d_in[4];
    const float* b_proj = (const float*)d_in[5];
    const float* gamma1 = (const float*)d_in[6];
    const float* beta1  = (const float*)d_in[7];
    const float* gamma2 = (const float*)d_in[8];
    const float* beta2  = (const float*)d_in[9];
    const float* w1     = (const float*)d_in[10];
    const float* b1     = (const float*)d_in[11];
    const float* w2     = (const float*)d_in[12];
    const float* b2     = (const float*)d_in[13];
    float* out = (float*)d_out;

    float *p_x2;
    __half *p_hh, *p_wqkv, *p_qkv, *p_o, *p_h2h, *p_ffn, *p_wp, *p_w1, *p_w2;
    cudaGetSymbolAddress((void**)&p_hh,   g_hh);
    cudaGetSymbolAddress((void**)&p_wqkv, g_wqkv);
    cudaGetSymbolAddress((void**)&p_qkv,  g_qkv);
    cudaGetSymbolAddress((void**)&p_o,    g_o);
    cudaGetSymbolAddress((void**)&p_x2,   g_x2);
    cudaGetSymbolAddress((void**)&p_h2h,  g_h2h);
    cudaGetSymbolAddress((void**)&p_ffn,  g_ffn);
    cudaGetSymbolAddress((void**)&p_wp,   g_wp);
    cudaGetSymbolAddress((void**)&p_w1,   g_w1);
    cudaGetSymbolAddress((void**)&p_w2,   g_w2);

    cudaFuncSetAttribute(mm_fp16<0, true>,  cudaFuncAttributeMaxDynamicSharedMemorySize, MM_SMEM4);
    cudaFuncSetAttribute(mm_fp16<2, true>,  cudaFuncAttributeMaxDynamicSharedMemorySize, MM_SMEM4);
    cudaFuncSetAttribute(mm_fp16<3, false>, cudaFuncAttributeMaxDynamicSharedMemorySize, MM_SMEM4);

    const int CVT_TOTAL4 = (EE * EE + EE * DFF + DFF * EE) / 4;

    // 1) LN1 (fp16 out, single pass)
    ln_kernel<<<NTOK, 256>>>(x, gamma1, beta1, p_hh);
    // 2) pack qkv weights + convert all other weights
    pack_w_kernel<<<(3 * EE * EE) / 256, 256>>>(wq, wk, wv, p_wqkv);
    cvtw_all_kernel<<<(CVT_TOTAL4 + 255) / 256, 256>>>(
        (const float4*)w_proj, (const float4*)w1, (const float4*)w2,
        (__half2*)p_wp, (__half2*)p_w1, (__half2*)p_w2);
    // 3) QKV = h @ Wqkv (fp16 out)
    mm_fp16<0, true><<<dim3(3 * EE / 128, NTOK / 128), 128, MM_SMEM4>>>(p_hh, p_wqkv, nullptr, nullptr, p_qkv, NTOK, 3 * EE, EE);
    // 4-6) fused flash attention (fp16)
    flash_kernel<<<dim3(TT / 64, BHN), 128>>>(p_qkv, p_o);
    // 7) x2 = h + O @ w_proj + b_proj (fp32 out, fp16 residual)
    mm_fp16<3, false><<<dim3(EE / 128, NTOK / 128), 128, MM_SMEM4>>>(p_o, p_wp, b_proj, p_hh, p_x2, NTOK, EE, EE);
    // 8) LN2 (fp16 out, single pass)
    ln_kernel<<<NTOK, 256>>>(p_x2, gamma2, beta2, p_h2h);
    // 9) ffn = relu(h2 @ w1 + b1) (fp16 out)
    mm_fp16<2, true><<<dim3(DFF / 128, NTOK / 128), 128, MM_SMEM4>>>(p_h2h, p_w1, b1, nullptr, p_ffn, NTOK, DFF, EE);
    // 10) out = h2 + ffn @ w2 + b2 (fp32 out, fp16 residual)
    mm_fp16<3, false><<<dim3(EE / 128, NTOK / 128), 128, MM_SMEM4>>>(p_ffn, p_w2, b2, p_h2h, out, NTOK, EE, DFF);
}